// round 5
// baseline (speedup 1.0000x reference)
#include <cuda_runtime.h>
#include <cuda_bf16.h>
#include <cstdint>

#define B_    256
#define NI    64
#define L_    128
#define H_    128
#define K_    40
#define MTOT  (B_ * K_)          /* 10240 rows */
#define GATES 384

typedef unsigned long long ull;

// ---------------------------------------------------------------------------
// Device scratch
// ---------------------------------------------------------------------------
__device__ __align__(256) __nv_bfloat16 g_xhi[MTOT * H_];
__device__ __align__(256) __nv_bfloat16 g_xlo[MTOT * H_];
__device__ __align__(256) __nv_bfloat16 g_hhi[MTOT * H_];
__device__ __align__(256) __nv_bfloat16 g_hlo[MTOT * H_];
__device__ __align__(256) float         g_h32[MTOT * H_];
__device__ __align__(256) __nv_bfloat16 g_h2hi[MTOT * H_];
__device__ __align__(256) __nv_bfloat16 g_h2lo[MTOT * H_];
__device__ __align__(256) float         g_h232[MTOT * H_];
__device__ __align__(256) __nv_bfloat16 g_wih_hi[GATES * H_];
__device__ __align__(256) __nv_bfloat16 g_wih_lo[GATES * H_];
__device__ __align__(256) __nv_bfloat16 g_whh_hi[GATES * H_];
__device__ __align__(256) __nv_bfloat16 g_whh_lo[GATES * H_];

// ---------------------------------------------------------------------------
// Helpers
// ---------------------------------------------------------------------------
__device__ __forceinline__ uint32_t smem_u32(const void* p) {
    uint32_t a;
    asm("{ .reg .u64 t; cvta.to.shared.u64 t, %1; cvt.u32.u64 %0, t; }"
        : "=r"(a) : "l"(p));
    return a;
}
__device__ __forceinline__ void cp16(uint32_t dst, const void* src) {
    asm volatile("cp.async.cg.shared.global [%0], [%1], 16;"
                 :: "r"(dst), "l"(src) : "memory");
}
#define CP_COMMIT() asm volatile("cp.async.commit_group;" ::: "memory")
#define CP_WAIT0()  asm volatile("cp.async.wait_group 0;" ::: "memory")

__device__ __forceinline__ void ldm4(uint32_t* a, uint32_t addr) {
    asm volatile("ldmatrix.sync.aligned.m8n8.x4.shared.b16 {%0,%1,%2,%3}, [%4];"
                 : "=r"(a[0]), "=r"(a[1]), "=r"(a[2]), "=r"(a[3]) : "r"(addr));
}
__device__ __forceinline__ float ldsf(uint32_t addr) {
    float v; asm volatile("ld.shared.f32 %0, [%1];" : "=f"(v) : "r"(addr));
    return v;
}
__device__ __forceinline__ void sts2(uint32_t addr, float a, float b) {
    asm volatile("st.shared.v2.f32 [%0], {%1,%2};"
                 :: "r"(addr), "f"(a), "f"(b) : "memory");
}
__device__ __forceinline__ void hmma(float* c, const uint32_t* a,
                                     uint32_t b0, uint32_t b1) {
    asm volatile("mma.sync.aligned.m16n8k16.row.col.f32.bf16.bf16.f32 "
                 "{%0,%1,%2,%3}, {%4,%5,%6,%7}, {%8,%9}, {%0,%1,%2,%3};"
                 : "+f"(c[0]), "+f"(c[1]), "+f"(c[2]), "+f"(c[3])
                 : "r"(a[0]), "r"(a[1]), "r"(a[2]), "r"(a[3]),
                   "r"(b0), "r"(b1));
}

__device__ __forceinline__ ull pk2(float v) {
    ull r; asm("mov.b64 %0, {%1, %1};" : "=l"(r) : "f"(v)); return r;
}
__device__ __forceinline__ float2 upk(ull v) {
    float2 f; asm("mov.b64 {%0, %1}, %2;" : "=f"(f.x), "=f"(f.y) : "l"(v)); return f;
}
__device__ __forceinline__ void fma2(ull& d, ull a, ull b) {
    asm("fma.rn.f32x2 %0, %1, %2, %0;" : "+l"(d) : "l"(a), "l"(b));
}
__device__ __forceinline__ ull ld2(const float* p) { return *(const ull*)p; }

__device__ __forceinline__ float sigm(float x) {
    return __fdividef(1.0f, 1.0f + __expf(-x));
}
__device__ __forceinline__ float tanh_(float x) {
    return __fdividef(2.0f, 1.0f + __expf(-2.0f * x)) - 1.0f;
}
__device__ __forceinline__ void split_store(float v, __nv_bfloat16* hi,
                                            __nv_bfloat16* lo, int idx) {
    __nv_bfloat16 h = __float2bfloat16(v);
    hi[idx] = h;
    lo[idx] = __float2bfloat16(v - __bfloat162float(h));
}

// ---------------------------------------------------------------------------
// K1: split weights into bf16 hi/lo
// ---------------------------------------------------------------------------
__global__ void prep_kernel(const float* __restrict__ w_ih,
                            const float* __restrict__ w_hh) {
    int idx = blockIdx.x * blockDim.x + threadIdx.x;
    if (idx < GATES * H_) {
        split_store(w_ih[idx], g_wih_hi, g_wih_lo, idx);
        split_store(w_hh[idx], g_whh_hi, g_whh_lo, idx);
    }
}

// ---------------------------------------------------------------------------
// K2: gather + adj GEMM -> x (a) splits, h (ev) splits + fp32 hold.
// ---------------------------------------------------------------------------
__global__ __launch_bounds__(256, 1)
void gather_adj_kernel(const float* __restrict__ seq_out,
                       const int*   __restrict__ target_idxs,
                       const int*   __restrict__ nid2rows,
                       const int*   __restrict__ ev_nids,
                       const float* __restrict__ adj,
                       const float* __restrict__ adj_bias) {
    __shared__ float s_h[K_ * H_];
    __shared__ float s_adj[K_ * K_];

    const int b    = blockIdx.x;
    const int tid  = threadIdx.x;
    const int warp = tid >> 5;
    const int lane = tid & 31;
    const int r0   = warp * 5;
    const int c0   = lane * 2;
    const int c1   = lane * 2 + 64;

    for (int i = tid; i < K_ * K_; i += 256)
        s_adj[i] = adj[b * K_ * K_ + i];

    #pragma unroll
    for (int rr = 0; rr < 5; rr++) {
        int k   = r0 + rr;
        int nid = ev_nids[b * K_ + k];
        int row = nid2rows[b * NI + nid];
        long long gi = (long long)b * NI + row;
        int t = target_idxs[gi];
        const float4* src = reinterpret_cast<const float4*>(
            seq_out + (gi * L_ + t) * (long long)H_);
        reinterpret_cast<float4*>(s_h + k * H_)[lane] = src[lane];
    }
    __syncthreads();

    ull bias0 = ld2(adj_bias + c0);
    ull bias1 = ld2(adj_bias + c1);
    ull acc[5][2];
    #pragma unroll
    for (int r = 0; r < 5; r++) { acc[r][0] = bias0; acc[r][1] = bias1; }

    for (int i = 0; i < K_; i++) {
        ull e0 = ld2(s_h + i * H_ + c0);
        ull e1 = ld2(s_h + i * H_ + c1);
        #pragma unroll
        for (int r = 0; r < 5; r++) {
            ull av = pk2(s_adj[i * K_ + r0 + r]);
            fma2(acc[r][0], av, e0);
            fma2(acc[r][1], av, e1);
        }
    }

    #pragma unroll
    for (int r = 0; r < 5; r++) {
        int gr = b * K_ + r0 + r;
        float2 a0 = upk(acc[r][0]);
        float2 a1 = upk(acc[r][1]);
        split_store(a0.x, g_xhi, g_xlo, gr * H_ + c0);
        split_store(a0.y, g_xhi, g_xlo, gr * H_ + c0 + 1);
        split_store(a1.x, g_xhi, g_xlo, gr * H_ + c1);
        split_store(a1.y, g_xhi, g_xlo, gr * H_ + c1 + 1);

        float2 e0 = upk(ld2(s_h + (r0 + r) * H_ + c0));
        float2 e1 = upk(ld2(s_h + (r0 + r) * H_ + c1));
        g_h32[gr * H_ + c0]     = e0.x;
        g_h32[gr * H_ + c0 + 1] = e0.y;
        g_h32[gr * H_ + c1]     = e1.x;
        g_h32[gr * H_ + c1 + 1] = e1.y;
        split_store(e0.x, g_hhi, g_hlo, gr * H_ + c0);
        split_store(e0.y, g_hhi, g_hlo, gr * H_ + c0 + 1);
        split_store(e1.x, g_hhi, g_hlo, gr * H_ + c1);
        split_store(e1.y, g_hhi, g_hlo, gr * H_ + c1 + 1);
    }
}

// ---------------------------------------------------------------------------
// K3: one GRU pass via HMMA.  Grid (160, 4): CTA = 64 rows x 32 h-cols.
// 512 threads = 16 warps = 4 row-groups (16 rows) x 4 col-chunks (48 gate-cols).
// Warp = 1 m-tile x 6 n-tiles; 24 f32 acc.  B fragments via ldmatrix.x4
// (1 instr per 2 n-tiles).  3 emulation terms: xhi*whi + xhi*wlo + xlo*whi.
// ---------------------------------------------------------------------------
#define PITCH   272                       /* bytes per A/W smem row */
#define A_TSZ   (64 * PITCH)              /* 17408 */
#define SW_OFF  (4 * A_TSZ)               /* 69632 */
#define W_TSZ   (192 * PITCH)             /* 52224 */
#define SG_OFF  SW_OFF                    /* gate buf overlays W */
#define GPITCH  1552                      /* 388 f32 words per gate row */
#define SMEM_TOT (SW_OFF + 2 * W_TSZ)     /* 174080 */

__global__ __launch_bounds__(512, 1)
void gru_pass_kernel(const __nv_bfloat16* __restrict__ xhi,
                     const __nv_bfloat16* __restrict__ xlo,
                     const __nv_bfloat16* __restrict__ hhi,
                     const __nv_bfloat16* __restrict__ hlo,
                     const float* __restrict__ hold,
                     const __nv_bfloat16* __restrict__ wih_hi,
                     const __nv_bfloat16* __restrict__ wih_lo,
                     const __nv_bfloat16* __restrict__ whh_hi,
                     const __nv_bfloat16* __restrict__ whh_lo,
                     const float* __restrict__ b_ih,
                     const float* __restrict__ b_hh,
                     float* __restrict__ out32,
                     __nv_bfloat16* __restrict__ out_hi,
                     __nv_bfloat16* __restrict__ out_lo) {
    extern __shared__ __align__(16) char smem[];
    const uint32_t sb  = smem_u32(smem);
    const int tid   = threadIdx.x;
    const int wid   = tid >> 5;
    const int lane  = tid & 31;
    const int mrow0 = blockIdx.x * 64;
    const int ycol0 = blockIdx.y * 32;

    // ---- load A tiles (xhi, xlo, hhi, hlo): 64 rows x 128 bf16, pitch 272 --
    {
        const __nv_bfloat16* asrc[4] = {xhi, xlo, hhi, hlo};
        #pragma unroll
        for (int t4 = 0; t4 < 4; t4++) {
            const __nv_bfloat16* src = asrc[t4] + (size_t)mrow0 * H_;
            uint32_t dst = sb + t4 * A_TSZ;
            #pragma unroll
            for (int c = tid; c < 1024; c += 512) {     // 16B chunks
                int row = c >> 4, cw = c & 15;
                cp16(dst + row * PITCH + cw * 16, src + row * H_ + cw * 8);
            }
        }
    }
    // ---- load W tiles: 192 rows (ih r/z/n | hh r/z/n x 32 hcols), hi|lo ----
    {
        const __nv_bfloat16* wsrc[4] = {wih_hi, whh_hi, wih_lo, whh_lo};
        #pragma unroll
        for (int part = 0; part < 2; part++) {          // 0: hi, 1: lo
            uint32_t dst = sb + SW_OFF + part * W_TSZ;
            for (int c = tid; c < 3072; c += 512) {     // 192 rows x 16 chunks
                int gp = c >> 4, cw = c & 15;
                int side = gp / 96, rem = gp % 96;
                int gate = rem >> 5, hc = rem & 31;
                const __nv_bfloat16* src = wsrc[part * 2 + side]
                    + (size_t)(gate * H_ + ycol0 + hc) * H_ + cw * 8;
                cp16(dst + gp * PITCH + cw * 16, src);
            }
        }
    }
    CP_COMMIT();
    CP_WAIT0();
    __syncthreads();

    // ---- MMA main loop -----------------------------------------------------
    const int chunk = wid >> 2;            // 0..3 gate-col chunk (48 cols)
    const int rowg  = wid & 3;             // 0..3 row group (16 rows)
    const int side  = chunk >> 1;          // 0: gi (x), 1: gh (h)
    const int mrows = rowg * 16;

    float acc[6][4];
    #pragma unroll
    for (int j = 0; j < 6; j++)
        #pragma unroll
        for (int q = 0; q < 4; q++) acc[j][q] = 0.0f;

    // A ldmatrix.x4: lanes 0-15 rows 0-15 (k lo), 16-31 same rows (k hi)
    const uint32_t a_lanoff = (uint32_t)(lane & 15) * PITCH
                            + ((lane >> 4) & 1) * 16;
    // B ldmatrix.x4: m0 = n0-7 k-lo, m1 = n0-7 k-hi, m2 = n8-15 k-lo, m3 = n8-15 k-hi
    const uint32_t b_lanoff =
        (uint32_t)(chunk * 48 + (lane & 7) + ((lane >> 4) << 3)) * PITCH
        + ((lane >> 3) & 1) * 16;

    const int aTile[3] = {0, 0, 1};        // hi, hi, lo (offset by side*2)
    const int wBuf [3] = {0, 1, 0};        // whi, wlo, whi

    #pragma unroll
    for (int term = 0; term < 3; term++) {
        const uint32_t Abase = sb + (side * 2 + aTile[term]) * A_TSZ
                             + mrows * PITCH + a_lanoff;
        const uint32_t Bbase = sb + SW_OFF + wBuf[term] * W_TSZ + b_lanoff;
        #pragma unroll
        for (int ks = 0; ks < 8; ks++) {
            uint32_t a[4];
            ldm4(a, Abase + ks * 32);
            #pragma unroll
            for (int j2 = 0; j2 < 3; j2++) {
                uint32_t bfr[4];
                ldm4(bfr, Bbase + j2 * (16 * PITCH) + ks * 32);
                hmma(acc[2 * j2],     a, bfr[0], bfr[1]);
                hmma(acc[2 * j2 + 1], a, bfr[2], bfr[3]);
            }
        }
    }

    // ---- dump gates to smem (overlay W region) -----------------------------
    __syncthreads();
    {
        int row = mrows + (lane >> 2);
        #pragma unroll
        for (int j = 0; j < 6; j++) {
            int col = chunk * 48 + j * 8 + 2 * (lane & 3);
            uint32_t ad = sb + SG_OFF + row * GPITCH + col * 4;
            sts2(ad,              acc[j][0], acc[j][1]);
            sts2(ad + 8 * GPITCH, acc[j][2], acc[j][3]);
        }
    }
    __syncthreads();

    // ---- epilogue: combine gates -> h' -------------------------------------
    {
        const int hcol = tid & 31;
        const int rowb = tid >> 5;          // 0..15
        const int col  = ycol0 + hcol;
        const float bir = b_ih[col],       bhr = b_hh[col];
        const float biz = b_ih[128 + col], bhz = b_hh[128 + col];
        const float bin = b_ih[256 + col], bhn = b_hh[256 + col];
        #pragma unroll
        for (int rr = 0; rr < 4; rr++) {
            int row = rowb * 4 + rr;
            uint32_t base = sb + SG_OFF + row * GPITCH + hcol * 4;
            float gir = ldsf(base);
            float giz = ldsf(base + 32 * 4);
            float gin = ldsf(base + 64 * 4);
            float ghr = ldsf(base + 96 * 4);
            float ghz = ldsf(base + 128 * 4);
            float ghn = ldsf(base + 160 * 4);
            float r = sigm(gir + bir + ghr + bhr);
            float z = sigm(giz + biz + ghz + bhz);
            float n = tanh_(gin + bin + r * (ghn + bhn));
            long long idx = (long long)(mrow0 + row) * H_ + col;
            float ho = hold[idx];
            float hn = (1.0f - z) * n + z * ho;
            out32[idx] = hn;
            if (out_hi) split_store(hn, out_hi, out_lo, (int)idx);
        }
    }
}

// ---------------------------------------------------------------------------
extern "C" void kernel_launch(void* const* d_in, const int* in_sizes, int n_in,
                              void* d_out, int out_size) {
    const float* seq_out     = (const float*)d_in[0];
    const int*   target_idxs = (const int*)  d_in[1];
    const int*   nid2rows    = (const int*)  d_in[2];
    const int*   ev_nids     = (const int*)  d_in[3];
    const float* adj         = (const float*)d_in[4];
    const float* adj_bias    = (const float*)d_in[5];
    const float* w_ih        = (const float*)d_in[6];
    const float* w_hh        = (const float*)d_in[7];
    const float* b_ih        = (const float*)d_in[8];
    const float* b_hh        = (const float*)d_in[9];
    float* out = (float*)d_out;

    static bool attr_set = false;
    if (!attr_set) {
        cudaFuncSetAttribute(gru_pass_kernel,
                             cudaFuncAttributeMaxDynamicSharedMemorySize,
                             SMEM_TOT);
        attr_set = true;
    }

    prep_kernel<<<(GATES * H_ + 255) / 256, 256>>>(w_ih, w_hh);
    gather_adj_kernel<<<B_, 256>>>(seq_out, target_idxs, nid2rows, ev_nids,
                                   adj, adj_bias);

    __nv_bfloat16 *xhi_p, *xlo_p, *hhi_p, *hlo_p, *h2hi_p, *h2lo_p;
    __nv_bfloat16 *wihh_p, *wihl_p, *whhh_p, *whhl_p;
    float *h32_p, *h232_p;
    cudaGetSymbolAddress((void**)&xhi_p,  g_xhi);
    cudaGetSymbolAddress((void**)&xlo_p,  g_xlo);
    cudaGetSymbolAddress((void**)&hhi_p,  g_hhi);
    cudaGetSymbolAddress((void**)&hlo_p,  g_hlo);
    cudaGetSymbolAddress((void**)&h2hi_p, g_h2hi);
    cudaGetSymbolAddress((void**)&h2lo_p, g_h2lo);
    cudaGetSymbolAddress((void**)&h32_p,  g_h32);
    cudaGetSymbolAddress((void**)&h232_p, g_h232);
    cudaGetSymbolAddress((void**)&wihh_p, g_wih_hi);
    cudaGetSymbolAddress((void**)&wihl_p, g_wih_lo);
    cudaGetSymbolAddress((void**)&whhh_p, g_whh_hi);
    cudaGetSymbolAddress((void**)&whhl_p, g_whh_lo);

    dim3 grid(MTOT / 64, 4);
    // pass 1: x = a, h = ev  -> h1 (fp32 + bf16 splits into fresh buffers)
    gru_pass_kernel<<<grid, 512, SMEM_TOT>>>(
        xhi_p, xlo_p, hhi_p, hlo_p, h32_p,
        wihh_p, wihl_p, whhh_p, whhl_p, b_ih, b_hh,
        h232_p, h2hi_p, h2lo_p);
    // pass 2: x = h = h1 -> d_out
    gru_pass_kernel<<<grid, 512, SMEM_TOT>>>(
        h2hi_p, h2lo_p, h2hi_p, h2lo_p, h232_p,
        wihh_p, wihl_p, whhh_p, whhl_p, b_ih, b_hh,
        out, nullptr, nullptr);
}

// round 6
// speedup vs baseline: 1.2400x; 1.2400x over previous
#include <cuda_runtime.h>
#include <cuda_bf16.h>
#include <cstdint>

#define B_    256
#define NI    64
#define L_    128
#define H_    128
#define K_    40
#define MTOT  (B_ * K_)          /* 10240 rows */
#define GATES 384

typedef unsigned long long ull;

// ---------------------------------------------------------------------------
// Device scratch
// ---------------------------------------------------------------------------
__device__ __align__(256) __nv_bfloat16 g_xhi[MTOT * H_];
__device__ __align__(256) __nv_bfloat16 g_xlo[MTOT * H_];
__device__ __align__(256) __nv_bfloat16 g_hhi[MTOT * H_];
__device__ __align__(256) __nv_bfloat16 g_hlo[MTOT * H_];
__device__ __align__(256) float         g_h32[MTOT * H_];
__device__ __align__(256) __nv_bfloat16 g_h2hi[MTOT * H_];
__device__ __align__(256) __nv_bfloat16 g_h2lo[MTOT * H_];
__device__ __align__(256) float         g_h232[MTOT * H_];
__device__ __align__(256) __nv_bfloat16 g_wih_hi[GATES * H_];
__device__ __align__(256) __nv_bfloat16 g_wih_lo[GATES * H_];
__device__ __align__(256) __nv_bfloat16 g_whh_hi[GATES * H_];
__device__ __align__(256) __nv_bfloat16 g_whh_lo[GATES * H_];

// ---------------------------------------------------------------------------
// Helpers
// ---------------------------------------------------------------------------
__device__ __forceinline__ uint32_t smem_u32(const void* p) {
    uint32_t a;
    asm("{ .reg .u64 t; cvta.to.shared.u64 t, %1; cvt.u32.u64 %0, t; }"
        : "=r"(a) : "l"(p));
    return a;
}
__device__ __forceinline__ void cp16(uint32_t dst, const void* src) {
    asm volatile("cp.async.cg.shared.global [%0], [%1], 16;"
                 :: "r"(dst), "l"(src) : "memory");
}
#define CP_COMMIT() asm volatile("cp.async.commit_group;" ::: "memory")
#define CP_WAIT0()  asm volatile("cp.async.wait_group 0;" ::: "memory")

__device__ __forceinline__ void ldm4(uint32_t* a, uint32_t addr) {
    asm volatile("ldmatrix.sync.aligned.m8n8.x4.shared.b16 {%0,%1,%2,%3}, [%4];"
                 : "=r"(a[0]), "=r"(a[1]), "=r"(a[2]), "=r"(a[3]) : "r"(addr));
}
__device__ __forceinline__ float ldsf(uint32_t addr) {
    float v; asm volatile("ld.shared.f32 %0, [%1];" : "=f"(v) : "r"(addr));
    return v;
}
__device__ __forceinline__ void sts2(uint32_t addr, float a, float b) {
    asm volatile("st.shared.v2.f32 [%0], {%1,%2};"
                 :: "r"(addr), "f"(a), "f"(b) : "memory");
}
__device__ __forceinline__ void hmma(float* c, const uint32_t* a,
                                     uint32_t b0, uint32_t b1) {
    asm volatile("mma.sync.aligned.m16n8k16.row.col.f32.bf16.bf16.f32 "
                 "{%0,%1,%2,%3}, {%4,%5,%6,%7}, {%8,%9}, {%0,%1,%2,%3};"
                 : "+f"(c[0]), "+f"(c[1]), "+f"(c[2]), "+f"(c[3])
                 : "r"(a[0]), "r"(a[1]), "r"(a[2]), "r"(a[3]),
                   "r"(b0), "r"(b1));
}

__device__ __forceinline__ ull pk2(float v) {
    ull r; asm("mov.b64 %0, {%1, %1};" : "=l"(r) : "f"(v)); return r;
}
__device__ __forceinline__ float2 upk(ull v) {
    float2 f; asm("mov.b64 {%0, %1}, %2;" : "=f"(f.x), "=f"(f.y) : "l"(v)); return f;
}
__device__ __forceinline__ void fma2(ull& d, ull a, ull b) {
    asm("fma.rn.f32x2 %0, %1, %2, %0;" : "+l"(d) : "l"(a), "l"(b));
}
__device__ __forceinline__ ull ld2(const float* p) { return *(const ull*)p; }

__device__ __forceinline__ float sigm(float x) {
    return __fdividef(1.0f, 1.0f + __expf(-x));
}
__device__ __forceinline__ float tanh_(float x) {
    return __fdividef(2.0f, 1.0f + __expf(-2.0f * x)) - 1.0f;
}
__device__ __forceinline__ void split_store(float v, __nv_bfloat16* hi,
                                            __nv_bfloat16* lo, int idx) {
    __nv_bfloat16 h = __float2bfloat16(v);
    hi[idx] = h;
    lo[idx] = __float2bfloat16(v - __bfloat162float(h));
}

// ---------------------------------------------------------------------------
// K1: split weights into bf16 hi/lo
// ---------------------------------------------------------------------------
__global__ void prep_kernel(const float* __restrict__ w_ih,
                            const float* __restrict__ w_hh) {
    int idx = blockIdx.x * blockDim.x + threadIdx.x;
    if (idx < GATES * H_) {
        split_store(w_ih[idx], g_wih_hi, g_wih_lo, idx);
        split_store(w_hh[idx], g_whh_hi, g_whh_lo, idx);
    }
}

// ---------------------------------------------------------------------------
// K2: gather + adj GEMM -> x (a) splits, h (ev) splits + fp32 hold.
// ---------------------------------------------------------------------------
__global__ __launch_bounds__(256, 1)
void gather_adj_kernel(const float* __restrict__ seq_out,
                       const int*   __restrict__ target_idxs,
                       const int*   __restrict__ nid2rows,
                       const int*   __restrict__ ev_nids,
                       const float* __restrict__ adj,
                       const float* __restrict__ adj_bias) {
    __shared__ float s_h[K_ * H_];
    __shared__ float s_adj[K_ * K_];

    const int b    = blockIdx.x;
    const int tid  = threadIdx.x;
    const int warp = tid >> 5;
    const int lane = tid & 31;
    const int r0   = warp * 5;
    const int c0   = lane * 2;
    const int c1   = lane * 2 + 64;

    for (int i = tid; i < K_ * K_; i += 256)
        s_adj[i] = adj[b * K_ * K_ + i];

    #pragma unroll
    for (int rr = 0; rr < 5; rr++) {
        int k   = r0 + rr;
        int nid = ev_nids[b * K_ + k];
        int row = nid2rows[b * NI + nid];
        long long gi = (long long)b * NI + row;
        int t = target_idxs[gi];
        const float4* src = reinterpret_cast<const float4*>(
            seq_out + (gi * L_ + t) * (long long)H_);
        reinterpret_cast<float4*>(s_h + k * H_)[lane] = src[lane];
    }
    __syncthreads();

    ull bias0 = ld2(adj_bias + c0);
    ull bias1 = ld2(adj_bias + c1);
    ull acc[5][2];
    #pragma unroll
    for (int r = 0; r < 5; r++) { acc[r][0] = bias0; acc[r][1] = bias1; }

    for (int i = 0; i < K_; i++) {
        ull e0 = ld2(s_h + i * H_ + c0);
        ull e1 = ld2(s_h + i * H_ + c1);
        #pragma unroll
        for (int r = 0; r < 5; r++) {
            ull av = pk2(s_adj[i * K_ + r0 + r]);
            fma2(acc[r][0], av, e0);
            fma2(acc[r][1], av, e1);
        }
    }

    #pragma unroll
    for (int r = 0; r < 5; r++) {
        int gr = b * K_ + r0 + r;
        float2 a0 = upk(acc[r][0]);
        float2 a1 = upk(acc[r][1]);
        split_store(a0.x, g_xhi, g_xlo, gr * H_ + c0);
        split_store(a0.y, g_xhi, g_xlo, gr * H_ + c0 + 1);
        split_store(a1.x, g_xhi, g_xlo, gr * H_ + c1);
        split_store(a1.y, g_xhi, g_xlo, gr * H_ + c1 + 1);

        float2 e0 = upk(ld2(s_h + (r0 + r) * H_ + c0));
        float2 e1 = upk(ld2(s_h + (r0 + r) * H_ + c1));
        g_h32[gr * H_ + c0]     = e0.x;
        g_h32[gr * H_ + c0 + 1] = e0.y;
        g_h32[gr * H_ + c1]     = e1.x;
        g_h32[gr * H_ + c1 + 1] = e1.y;
        split_store(e0.x, g_hhi, g_hlo, gr * H_ + c0);
        split_store(e0.y, g_hhi, g_hlo, gr * H_ + c0 + 1);
        split_store(e1.x, g_hhi, g_hlo, gr * H_ + c1);
        split_store(e1.y, g_hhi, g_hlo, gr * H_ + c1 + 1);
    }
}

// ---------------------------------------------------------------------------
// K3: one GRU pass via HMMA, persistent-W pipelined.
// Grid (32, 4): CTA owns a 32-hcol chunk (192 gate cols) and 5 consecutive
// 64-row M-tiles.  W slice (192x128 hi+lo, 104 KB) loaded ONCE per CTA.
// Per tile: compute -> prefetch next A (cp.async) overlapped with gate dump
// + epilogue -> wait.  512 threads = 16 warps = 4 row-groups x 4 col-chunks.
// Warp = m16 x 6 n-tiles; 3 emulation terms xhi*whi + xhi*wlo + xlo*whi.
// ---------------------------------------------------------------------------
#define PITCH    272                      /* bytes per A/W smem row */
#define A_TSZ    (64 * PITCH)             /* 17408 */
#define SW_OFF   (4 * A_TSZ)              /* 69632 */
#define W_TSZ    (192 * PITCH)            /* 52224 */
#define SG_OFF   (SW_OFF + 2 * W_TSZ)     /* 174080 */
#define GPITCH   784                      /* 196 f32 words per gate row */
#define SMEM_TOT (SG_OFF + 64 * GPITCH)   /* 224256 */
#define NTILES   5

__global__ __launch_bounds__(512, 1)
void gru_pass_kernel(const __nv_bfloat16* __restrict__ xhi,
                     const __nv_bfloat16* __restrict__ xlo,
                     const __nv_bfloat16* __restrict__ hhi,
                     const __nv_bfloat16* __restrict__ hlo,
                     const float* __restrict__ hold,
                     const __nv_bfloat16* __restrict__ wih_hi,
                     const __nv_bfloat16* __restrict__ wih_lo,
                     const __nv_bfloat16* __restrict__ whh_hi,
                     const __nv_bfloat16* __restrict__ whh_lo,
                     const float* __restrict__ b_ih,
                     const float* __restrict__ b_hh,
                     float* __restrict__ out32,
                     __nv_bfloat16* __restrict__ out_hi,
                     __nv_bfloat16* __restrict__ out_lo) {
    extern __shared__ __align__(16) char smem[];
    const uint32_t sb  = smem_u32(smem);
    const int tid   = threadIdx.x;
    const int wid   = tid >> 5;
    const int lane  = tid & 31;
    const int ycol0 = blockIdx.y * 32;
    const int m0    = blockIdx.x * NTILES;      // first M-tile

    // ---- A tile prefetch (4 subtiles: xhi, xlo, hhi, hlo) ------------------
    const __nv_bfloat16* asrc[4] = {xhi, xlo, hhi, hlo};
    auto loadA = [&](int m) {
        #pragma unroll
        for (int t4 = 0; t4 < 4; t4++) {
            const __nv_bfloat16* src = asrc[t4] + (size_t)m * 64 * H_;
            uint32_t dst = sb + t4 * A_TSZ;
            #pragma unroll
            for (int c = tid; c < 1024; c += 512) {     // 16B chunks
                int row = c >> 4, cw = c & 15;
                cp16(dst + row * PITCH + cw * 16, src + row * H_ + cw * 8);
            }
        }
    };

    // ---- W load (once): 192 gate-rows x 128 k, hi then lo ------------------
    {
        const __nv_bfloat16* wsrc[4] = {wih_hi, whh_hi, wih_lo, whh_lo};
        #pragma unroll
        for (int part = 0; part < 2; part++) {
            uint32_t dst = sb + SW_OFF + part * W_TSZ;
            #pragma unroll
            for (int c = tid; c < 3072; c += 512) {     // 192 rows x 16 chunks
                int gp = c >> 4, cw = c & 15;
                int side = gp / 96, rem = gp % 96;
                int gate = rem >> 5, hc = rem & 31;
                const __nv_bfloat16* src = wsrc[part * 2 + side]
                    + (size_t)(gate * H_ + ycol0 + hc) * H_ + cw * 8;
                cp16(dst + gp * PITCH + cw * 16, src);
            }
        }
    }
    loadA(m0);
    CP_COMMIT();
    CP_WAIT0();
    __syncthreads();

    // ---- warp tiling constants ----------------------------------------------
    const int chunk = wid >> 2;            // 0..3 gate-col chunk (48 cols)
    const int rowg  = wid & 3;             // 0..3 row group (16 rows)
    const int side  = chunk >> 1;          // 0: gi (x), 1: gh (h)
    const int mrows = rowg * 16;

    const uint32_t a_lanoff = (uint32_t)(lane & 15) * PITCH
                            + ((lane >> 4) & 1) * 16;
    const uint32_t b_lanoff =
        (uint32_t)(chunk * 48 + (lane & 7) + ((lane >> 4) << 3)) * PITCH
        + ((lane >> 3) & 1) * 16;

    const int aTile[3] = {0, 0, 1};        // hi, hi, lo (offset by side*2)
    const int wBuf [3] = {0, 1, 0};        // whi, wlo, whi

    // epilogue constants
    const int e_hcol = tid & 31;
    const int e_rowb = tid >> 5;           // 0..15
    const int e_col  = ycol0 + e_hcol;
    const float bir = b_ih[e_col],       bhr = b_hh[e_col];
    const float biz = b_ih[128 + e_col], bhz = b_hh[128 + e_col];
    const float bin = b_ih[256 + e_col], bhn = b_hh[256 + e_col];

    #pragma unroll 1
    for (int it = 0; it < NTILES; it++) {
        const int m     = m0 + it;
        const int mrow0 = m * 64;

        // ---- MMA compute -----------------------------------------------------
        float acc[6][4];
        #pragma unroll
        for (int j = 0; j < 6; j++)
            #pragma unroll
            for (int q = 0; q < 4; q++) acc[j][q] = 0.0f;

        #pragma unroll
        for (int term = 0; term < 3; term++) {
            const uint32_t Abase = sb + (side * 2 + aTile[term]) * A_TSZ
                                 + mrows * PITCH + a_lanoff;
            const uint32_t Bbase = sb + SW_OFF + wBuf[term] * W_TSZ + b_lanoff;
            #pragma unroll
            for (int ks = 0; ks < 8; ks++) {
                uint32_t a[4];
                ldm4(a, Abase + ks * 32);
                #pragma unroll
                for (int j2 = 0; j2 < 3; j2++) {
                    uint32_t bfr[4];
                    ldm4(bfr, Bbase + j2 * (16 * PITCH) + ks * 32);
                    hmma(acc[2 * j2],     a, bfr[0], bfr[1]);
                    hmma(acc[2 * j2 + 1], a, bfr[2], bfr[3]);
                }
            }
        }
        __syncthreads();                    // A fully consumed, G free

        // ---- prefetch next A (overlaps dump + epilogue) -----------------------
        if (it + 1 < NTILES) { loadA(m + 1); CP_COMMIT(); }

        // ---- dump gates to smem G ---------------------------------------------
        {
            int row = mrows + (lane >> 2);
            #pragma unroll
            for (int j = 0; j < 6; j++) {
                int col = chunk * 48 + j * 8 + 2 * (lane & 3);
                uint32_t ad = sb + SG_OFF + row * GPITCH + col * 4;
                sts2(ad,              acc[j][0], acc[j][1]);
                sts2(ad + 8 * GPITCH, acc[j][2], acc[j][3]);
            }
        }
        __syncthreads();                    // G visible

        // ---- epilogue: combine gates -> h' ------------------------------------
        #pragma unroll
        for (int rr = 0; rr < 4; rr++) {
            int row = e_rowb * 4 + rr;
            uint32_t base = sb + SG_OFF + row * GPITCH + e_hcol * 4;
            float gir = ldsf(base);
            float giz = ldsf(base + 32 * 4);
            float gin = ldsf(base + 64 * 4);
            float ghr = ldsf(base + 96 * 4);
            float ghz = ldsf(base + 128 * 4);
            float ghn = ldsf(base + 160 * 4);
            float r = sigm(gir + bir + ghr + bhr);
            float z = sigm(giz + biz + ghz + bhz);
            float n = tanh_(gin + bin + r * (ghn + bhn));
            long long idx = (long long)(mrow0 + row) * H_ + e_col;
            float ho = hold[idx];
            float hn = (1.0f - z) * n + z * ho;
            out32[idx] = hn;
            if (out_hi) split_store(hn, out_hi, out_lo, (int)idx);
        }

        if (it + 1 < NTILES) { CP_WAIT0(); }
        __syncthreads();                    // next A ready / G reuse safe
    }
}

// ---------------------------------------------------------------------------
extern "C" void kernel_launch(void* const* d_in, const int* in_sizes, int n_in,
                              void* d_out, int out_size) {
    const float* seq_out     = (const float*)d_in[0];
    const int*   target_idxs = (const int*)  d_in[1];
    const int*   nid2rows    = (const int*)  d_in[2];
    const int*   ev_nids     = (const int*)  d_in[3];
    const float* adj         = (const float*)d_in[4];
    const float* adj_bias    = (const float*)d_in[5];
    const float* w_ih        = (const float*)d_in[6];
    const float* w_hh        = (const float*)d_in[7];
    const float* b_ih        = (const float*)d_in[8];
    const float* b_hh        = (const float*)d_in[9];
    float* out = (float*)d_out;

    static bool attr_set = false;
    if (!attr_set) {
        cudaFuncSetAttribute(gru_pass_kernel,
                             cudaFuncAttributeMaxDynamicSharedMemorySize,
                             SMEM_TOT);
        attr_set = true;
    }

    prep_kernel<<<(GATES * H_ + 255) / 256, 256>>>(w_ih, w_hh);
    gather_adj_kernel<<<B_, 256>>>(seq_out, target_idxs, nid2rows, ev_nids,
                                   adj, adj_bias);

    __nv_bfloat16 *xhi_p, *xlo_p, *hhi_p, *hlo_p, *h2hi_p, *h2lo_p;
    __nv_bfloat16 *wihh_p, *wihl_p, *whhh_p, *whhl_p;
    float *h32_p, *h232_p;
    cudaGetSymbolAddress((void**)&xhi_p,  g_xhi);
    cudaGetSymbolAddress((void**)&xlo_p,  g_xlo);
    cudaGetSymbolAddress((void**)&hhi_p,  g_hhi);
    cudaGetSymbolAddress((void**)&hlo_p,  g_hlo);
    cudaGetSymbolAddress((void**)&h2hi_p, g_h2hi);
    cudaGetSymbolAddress((void**)&h2lo_p, g_h2lo);
    cudaGetSymbolAddress((void**)&h32_p,  g_h32);
    cudaGetSymbolAddress((void**)&h232_p, g_h232);
    cudaGetSymbolAddress((void**)&wihh_p, g_wih_hi);
    cudaGetSymbolAddress((void**)&wihl_p, g_wih_lo);
    cudaGetSymbolAddress((void**)&whhh_p, g_whh_hi);
    cudaGetSymbolAddress((void**)&whhl_p, g_whh_lo);

    dim3 grid(MTOT / (64 * NTILES), 4);    // (32, 4)
    // pass 1: x = a, h = ev  -> h1 (fp32 + bf16 splits into fresh buffers)
    gru_pass_kernel<<<grid, 512, SMEM_TOT>>>(
        xhi_p, xlo_p, hhi_p, hlo_p, h32_p,
        wihh_p, wihl_p, whhh_p, whhl_p, b_ih, b_hh,
        h232_p, h2hi_p, h2lo_p);
    // pass 2: x = h = h1 -> d_out
    gru_pass_kernel<<<grid, 512, SMEM_TOT>>>(
        h2hi_p, h2lo_p, h2hi_p, h2lo_p, h232_p,
        wihh_p, wihl_p, whhh_p, whhl_p, b_ih, b_hh,
        out, nullptr, nullptr);
}

// round 7
// speedup vs baseline: 1.2721x; 1.0258x over previous
#include <cuda_runtime.h>
#include <cuda_bf16.h>
#include <cstdint>

#define B_    256
#define NI    64
#define L_    128
#define H_    128
#define K_    40
#define MTOT  (B_ * K_)          /* 10240 rows */
#define GATES 384

typedef unsigned long long ull;

// ---------------------------------------------------------------------------
// Device scratch
// ---------------------------------------------------------------------------
__device__ __align__(256) __nv_bfloat16 g_xhi[MTOT * H_];
__device__ __align__(256) __nv_bfloat16 g_xlo[MTOT * H_];
__device__ __align__(256) __nv_bfloat16 g_hhi[MTOT * H_];
__device__ __align__(256) __nv_bfloat16 g_hlo[MTOT * H_];
__device__ __align__(256) float         g_h32[MTOT * H_];
__device__ __align__(256) __nv_bfloat16 g_h2hi[MTOT * H_];
__device__ __align__(256) __nv_bfloat16 g_h2lo[MTOT * H_];
__device__ __align__(256) float         g_h232[MTOT * H_];
__device__ __align__(256) __nv_bfloat16 g_wih_hi[GATES * H_];
__device__ __align__(256) __nv_bfloat16 g_wih_lo[GATES * H_];
__device__ __align__(256) __nv_bfloat16 g_whh_hi[GATES * H_];
__device__ __align__(256) __nv_bfloat16 g_whh_lo[GATES * H_];

// ---------------------------------------------------------------------------
// Helpers
// ---------------------------------------------------------------------------
__device__ __forceinline__ uint32_t smem_u32(const void* p) {
    uint32_t a;
    asm("{ .reg .u64 t; cvta.to.shared.u64 t, %1; cvt.u32.u64 %0, t; }"
        : "=r"(a) : "l"(p));
    return a;
}
__device__ __forceinline__ void cp16(uint32_t dst, const void* src) {
    asm volatile("cp.async.cg.shared.global [%0], [%1], 16;"
                 :: "r"(dst), "l"(src) : "memory");
}
#define CP_COMMIT() asm volatile("cp.async.commit_group;" ::: "memory")
#define CP_WAIT0()  asm volatile("cp.async.wait_group 0;" ::: "memory")
#define NB(id)      asm volatile("bar.sync %0, 128;" :: "r"((id) + 1) : "memory")

__device__ __forceinline__ void ldm4(uint32_t* a, uint32_t addr) {
    asm volatile("ldmatrix.sync.aligned.m8n8.x4.shared.b16 {%0,%1,%2,%3}, [%4];"
                 : "=r"(a[0]), "=r"(a[1]), "=r"(a[2]), "=r"(a[3]) : "r"(addr));
}
__device__ __forceinline__ float ldsf(uint32_t addr) {
    float v; asm volatile("ld.shared.f32 %0, [%1];" : "=f"(v) : "r"(addr));
    return v;
}
__device__ __forceinline__ void sts2(uint32_t addr, float a, float b) {
    asm volatile("st.shared.v2.f32 [%0], {%1,%2};"
                 :: "r"(addr), "f"(a), "f"(b) : "memory");
}
__device__ __forceinline__ void hmma(float* c, const uint32_t* a,
                                     uint32_t b0, uint32_t b1) {
    asm volatile("mma.sync.aligned.m16n8k16.row.col.f32.bf16.bf16.f32 "
                 "{%0,%1,%2,%3}, {%4,%5,%6,%7}, {%8,%9}, {%0,%1,%2,%3};"
                 : "+f"(c[0]), "+f"(c[1]), "+f"(c[2]), "+f"(c[3])
                 : "r"(a[0]), "r"(a[1]), "r"(a[2]), "r"(a[3]),
                   "r"(b0), "r"(b1));
}

__device__ __forceinline__ ull pk2(float v) {
    ull r; asm("mov.b64 %0, {%1, %1};" : "=l"(r) : "f"(v)); return r;
}
__device__ __forceinline__ float2 upk(ull v) {
    float2 f; asm("mov.b64 {%0, %1}, %2;" : "=f"(f.x), "=f"(f.y) : "l"(v)); return f;
}
__device__ __forceinline__ void fma2(ull& d, ull a, ull b) {
    asm("fma.rn.f32x2 %0, %1, %2, %0;" : "+l"(d) : "l"(a), "l"(b));
}
__device__ __forceinline__ ull ld2(const float* p) { return *(const ull*)p; }

__device__ __forceinline__ float sigm(float x) {
    return __fdividef(1.0f, 1.0f + __expf(-x));
}
__device__ __forceinline__ float tanh_(float x) {
    return __fdividef(2.0f, 1.0f + __expf(-2.0f * x)) - 1.0f;
}
__device__ __forceinline__ void split_store(float v, __nv_bfloat16* hi,
                                            __nv_bfloat16* lo, int idx) {
    __nv_bfloat16 h = __float2bfloat16(v);
    hi[idx] = h;
    lo[idx] = __float2bfloat16(v - __bfloat162float(h));
}

// ---------------------------------------------------------------------------
// K1: split weights into bf16 hi/lo
// ---------------------------------------------------------------------------
__global__ void prep_kernel(const float* __restrict__ w_ih,
                            const float* __restrict__ w_hh) {
    int idx = blockIdx.x * blockDim.x + threadIdx.x;
    if (idx < GATES * H_) {
        split_store(w_ih[idx], g_wih_hi, g_wih_lo, idx);
        split_store(w_hh[idx], g_whh_hi, g_whh_lo, idx);
    }
}

// ---------------------------------------------------------------------------
// K2: gather + adj GEMM -> x (a) splits, h (ev) splits + fp32 hold.
// ---------------------------------------------------------------------------
__global__ __launch_bounds__(256, 1)
void gather_adj_kernel(const float* __restrict__ seq_out,
                       const int*   __restrict__ target_idxs,
                       const int*   __restrict__ nid2rows,
                       const int*   __restrict__ ev_nids,
                       const float* __restrict__ adj,
                       const float* __restrict__ adj_bias) {
    __shared__ float s_h[K_ * H_];
    __shared__ float s_adj[K_ * K_];

    const int b    = blockIdx.x;
    const int tid  = threadIdx.x;
    const int warp = tid >> 5;
    const int lane = tid & 31;
    const int r0   = warp * 5;
    const int c0   = lane * 2;
    const int c1   = lane * 2 + 64;

    for (int i = tid; i < K_ * K_; i += 256)
        s_adj[i] = adj[b * K_ * K_ + i];

    #pragma unroll
    for (int rr = 0; rr < 5; rr++) {
        int k   = r0 + rr;
        int nid = ev_nids[b * K_ + k];
        int row = nid2rows[b * NI + nid];
        long long gi = (long long)b * NI + row;
        int t = target_idxs[gi];
        const float4* src = reinterpret_cast<const float4*>(
            seq_out + (gi * L_ + t) * (long long)H_);
        reinterpret_cast<float4*>(s_h + k * H_)[lane] = src[lane];
    }
    __syncthreads();

    ull bias0 = ld2(adj_bias + c0);
    ull bias1 = ld2(adj_bias + c1);
    ull acc[5][2];
    #pragma unroll
    for (int r = 0; r < 5; r++) { acc[r][0] = bias0; acc[r][1] = bias1; }

    for (int i = 0; i < K_; i++) {
        ull e0 = ld2(s_h + i * H_ + c0);
        ull e1 = ld2(s_h + i * H_ + c1);
        #pragma unroll
        for (int r = 0; r < 5; r++) {
            ull av = pk2(s_adj[i * K_ + r0 + r]);
            fma2(acc[r][0], av, e0);
            fma2(acc[r][1], av, e1);
        }
    }

    #pragma unroll
    for (int r = 0; r < 5; r++) {
        int gr = b * K_ + r0 + r;
        float2 a0 = upk(acc[r][0]);
        float2 a1 = upk(acc[r][1]);
        split_store(a0.x, g_xhi, g_xlo, gr * H_ + c0);
        split_store(a0.y, g_xhi, g_xlo, gr * H_ + c0 + 1);
        split_store(a1.x, g_xhi, g_xlo, gr * H_ + c1);
        split_store(a1.y, g_xhi, g_xlo, gr * H_ + c1 + 1);

        float2 e0 = upk(ld2(s_h + (r0 + r) * H_ + c0));
        float2 e1 = upk(ld2(s_h + (r0 + r) * H_ + c1));
        g_h32[gr * H_ + c0]     = e0.x;
        g_h32[gr * H_ + c0 + 1] = e0.y;
        g_h32[gr * H_ + c1]     = e1.x;
        g_h32[gr * H_ + c1 + 1] = e1.y;
        split_store(e0.x, g_hhi, g_hlo, gr * H_ + c0);
        split_store(e0.y, g_hhi, g_hlo, gr * H_ + c0 + 1);
        split_store(e1.x, g_hhi, g_hlo, gr * H_ + c1);
        split_store(e1.y, g_hhi, g_hlo, gr * H_ + c1 + 1);
    }
}

// ---------------------------------------------------------------------------
// K3: one GRU pass via HMMA, persistent-W, 4 independent row-group pipelines.
// Grid (32, 4): CTA owns a 32-hcol chunk (192 gate cols) and 5 consecutive
// 64-row M-tiles.  W slice loaded ONCE per CTA (full __syncthreads only there).
// 16 warps = 4 row-groups x 4 col-chunks.  Each row-group (4 warps, disjoint
// 16-row A slice / gate rows / outputs) runs its own tile pipeline with
// named barriers (bar.sync rowg+1, 128), so one group's epilogue overlaps
// the other groups' HMMA.
// ---------------------------------------------------------------------------
#define PITCH    272                      /* bytes per A/W smem row */
#define A_TSZ    (64 * PITCH)             /* 17408 */
#define SW_OFF   (4 * A_TSZ)              /* 69632 */
#define W_TSZ    (192 * PITCH)            /* 52224 */
#define SG_OFF   (SW_OFF + 2 * W_TSZ)     /* 174080 */
#define GPITCH   784                      /* 196 f32 words per gate row */
#define SMEM_TOT (SG_OFF + 64 * GPITCH)   /* 224256 */
#define NTILES   5

__global__ __launch_bounds__(512, 1)
void gru_pass_kernel(const __nv_bfloat16* __restrict__ xhi,
                     const __nv_bfloat16* __restrict__ xlo,
                     const __nv_bfloat16* __restrict__ hhi,
                     const __nv_bfloat16* __restrict__ hlo,
                     const float* __restrict__ hold,
                     const __nv_bfloat16* __restrict__ wih_hi,
                     const __nv_bfloat16* __restrict__ wih_lo,
                     const __nv_bfloat16* __restrict__ whh_hi,
                     const __nv_bfloat16* __restrict__ whh_lo,
                     const float* __restrict__ b_ih,
                     const float* __restrict__ b_hh,
                     float* __restrict__ out32,
                     __nv_bfloat16* __restrict__ out_hi,
                     __nv_bfloat16* __restrict__ out_lo) {
    extern __shared__ __align__(16) char smem[];
    const uint32_t sb  = smem_u32(smem);
    const int tid   = threadIdx.x;
    const int wid   = tid >> 5;
    const int lane  = tid & 31;
    const int ycol0 = blockIdx.y * 32;
    const int m0    = blockIdx.x * NTILES;      // first M-tile

    const int chunk = wid >> 2;            // 0..3 gate-col chunk (48 cols)
    const int rowg  = wid & 3;             // 0..3 row group (16 rows)
    const int side  = chunk >> 1;          // 0: gi (x), 1: gh (h)
    const int mrows = rowg * 16;
    const int gt    = chunk * 32 + lane;   // group-local tid 0..127

    // ---- per-group A slice prefetch (16 rows of xhi, xlo, hhi, hlo) --------
    const __nv_bfloat16* asrc[4] = {xhi, xlo, hhi, hlo};
    auto loadA = [&](int m) {
        #pragma unroll
        for (int t4 = 0; t4 < 4; t4++) {
            const __nv_bfloat16* src = asrc[t4]
                + ((size_t)m * 64 + mrows) * H_;
            uint32_t dst = sb + t4 * A_TSZ + mrows * PITCH;
            #pragma unroll
            for (int c = gt; c < 256; c += 128) {       // 16 rows x 16 chunks
                int row = c >> 4, cw = c & 15;
                cp16(dst + row * PITCH + cw * 16, src + row * H_ + cw * 8);
            }
        }
    };

    // ---- W load (once): 192 gate-rows x 128 k, hi then lo ------------------
    {
        const __nv_bfloat16* wsrc[4] = {wih_hi, whh_hi, wih_lo, whh_lo};
        #pragma unroll
        for (int part = 0; part < 2; part++) {
            uint32_t dst = sb + SW_OFF + part * W_TSZ;
            #pragma unroll
            for (int c = tid; c < 3072; c += 512) {     // 192 rows x 16 chunks
                int gp = c >> 4, cw = c & 15;
                int sde = gp / 96, rem = gp % 96;
                int gate = rem >> 5, hc = rem & 31;
                const __nv_bfloat16* src = wsrc[part * 2 + sde]
                    + (size_t)(gate * H_ + ycol0 + hc) * H_ + cw * 8;
                cp16(dst + gp * PITCH + cw * 16, src);
            }
        }
    }
    loadA(m0);
    CP_COMMIT();
    CP_WAIT0();
    __syncthreads();                       // W + first A visible to all

    // ---- tiling constants ---------------------------------------------------
    const uint32_t a_lanoff = (uint32_t)(lane & 15) * PITCH
                            + ((lane >> 4) & 1) * 16;
    const uint32_t b_lanoff =
        (uint32_t)(chunk * 48 + (lane & 7) + ((lane >> 4) << 3)) * PITCH
        + ((lane >> 3) & 1) * 16;

    const int aTile[3] = {0, 0, 1};        // hi, hi, lo (offset by side*2)
    const int wBuf [3] = {0, 1, 0};        // whi, wlo, whi

    // epilogue constants: group handles its own 16 rows x 32 cols
    const int e_col  = ycol0 + lane;
    const float bir = b_ih[e_col],       bhr = b_hh[e_col];
    const float biz = b_ih[128 + e_col], bhz = b_hh[128 + e_col];
    const float bin = b_ih[256 + e_col], bhn = b_hh[256 + e_col];

    #pragma unroll 1
    for (int it = 0; it < NTILES; it++) {
        const int m     = m0 + it;
        const int mrow0 = m * 64;

        // ---- MMA compute -----------------------------------------------------
        float acc[6][4];
        #pragma unroll
        for (int j = 0; j < 6; j++)
            #pragma unroll
            for (int q = 0; q < 4; q++) acc[j][q] = 0.0f;

        #pragma unroll
        for (int term = 0; term < 3; term++) {
            const uint32_t Abase = sb + (side * 2 + aTile[term]) * A_TSZ
                                 + mrows * PITCH + a_lanoff;
            const uint32_t Bbase = sb + SW_OFF + wBuf[term] * W_TSZ + b_lanoff;
            #pragma unroll
            for (int ks = 0; ks < 8; ks++) {
                uint32_t a[4];
                ldm4(a, Abase + ks * 32);
                #pragma unroll
                for (int j2 = 0; j2 < 3; j2++) {
                    uint32_t bfr[4];
                    ldm4(bfr, Bbase + j2 * (16 * PITCH) + ks * 32);
                    hmma(acc[2 * j2],     a, bfr[0], bfr[1]);
                    hmma(acc[2 * j2 + 1], a, bfr[2], bfr[3]);
                }
            }
        }
        NB(rowg);                          // group's A slice consumed, G free

        // ---- prefetch next A slice (overlaps dump + epilogue) ------------------
        if (it + 1 < NTILES) { loadA(m + 1); CP_COMMIT(); }

        // ---- dump gates to smem G (group's 16 rows) ----------------------------
        {
            int row = mrows + (lane >> 2);
            #pragma unroll
            for (int j = 0; j < 6; j++) {
                int col = chunk * 48 + j * 8 + 2 * (lane & 3);
                uint32_t ad = sb + SG_OFF + row * GPITCH + col * 4;
                sts2(ad,              acc[j][0], acc[j][1]);
                sts2(ad + 8 * GPITCH, acc[j][2], acc[j][3]);
            }
        }
        NB(rowg);                          // G visible within group

        // ---- epilogue: combine gates -> h' (rows mrows + chunk*4 .. +4) --------
        #pragma unroll
        for (int rr = 0; rr < 4; rr++) {
            int row = mrows + chunk * 4 + rr;
            uint32_t base = sb + SG_OFF + row * GPITCH + lane * 4;
            float gir = ldsf(base);
            float giz = ldsf(base + 32 * 4);
            float gin = ldsf(base + 64 * 4);
            float ghr = ldsf(base + 96 * 4);
            float ghz = ldsf(base + 128 * 4);
            float ghn = ldsf(base + 160 * 4);
            float r = sigm(gir + bir + ghr + bhr);
            float z = sigm(giz + biz + ghz + bhz);
            float n = tanh_(gin + bin + r * (ghn + bhn));
            long long idx = (long long)(mrow0 + row) * H_ + e_col;
            float ho = hold[idx];
            float hn = (1.0f - z) * n + z * ho;
            out32[idx] = hn;
            if (out_hi) split_store(hn, out_hi, out_lo, (int)idx);
        }

        if (it + 1 < NTILES) { CP_WAIT0(); }
        NB(rowg);                          // next A ready / G reuse safe
    }
}

// ---------------------------------------------------------------------------
extern "C" void kernel_launch(void* const* d_in, const int* in_sizes, int n_in,
                              void* d_out, int out_size) {
    const float* seq_out     = (const float*)d_in[0];
    const int*   target_idxs = (const int*)  d_in[1];
    const int*   nid2rows    = (const int*)  d_in[2];
    const int*   ev_nids     = (const int*)  d_in[3];
    const float* adj         = (const float*)d_in[4];
    const float* adj_bias    = (const float*)d_in[5];
    const float* w_ih        = (const float*)d_in[6];
    const float* w_hh        = (const float*)d_in[7];
    const float* b_ih        = (const float*)d_in[8];
    const float* b_hh        = (const float*)d_in[9];
    float* out = (float*)d_out;

    static bool attr_set = false;
    if (!attr_set) {
        cudaFuncSetAttribute(gru_pass_kernel,
                             cudaFuncAttributeMaxDynamicSharedMemorySize,
                             SMEM_TOT);
        attr_set = true;
    }

    prep_kernel<<<(GATES * H_ + 255) / 256, 256>>>(w_ih, w_hh);
    gather_adj_kernel<<<B_, 256>>>(seq_out, target_idxs, nid2rows, ev_nids,
                                   adj, adj_bias);

    __nv_bfloat16 *xhi_p, *xlo_p, *hhi_p, *hlo_p, *h2hi_p, *h2lo_p;
    __nv_bfloat16 *wihh_p, *wihl_p, *whhh_p, *whhl_p;
    float *h32_p, *h232_p;
    cudaGetSymbolAddress((void**)&xhi_p,  g_xhi);
    cudaGetSymbolAddress((void**)&xlo_p,  g_xlo);
    cudaGetSymbolAddress((void**)&hhi_p,  g_hhi);
    cudaGetSymbolAddress((void**)&hlo_p,  g_hlo);
    cudaGetSymbolAddress((void**)&h2hi_p, g_h2hi);
    cudaGetSymbolAddress((void**)&h2lo_p, g_h2lo);
    cudaGetSymbolAddress((void**)&h32_p,  g_h32);
    cudaGetSymbolAddress((void**)&h232_p, g_h232);
    cudaGetSymbolAddress((void**)&wihh_p, g_wih_hi);
    cudaGetSymbolAddress((void**)&wihl_p, g_wih_lo);
    cudaGetSymbolAddress((void**)&whhh_p, g_whh_hi);
    cudaGetSymbolAddress((void**)&whhl_p, g_whh_lo);

    dim3 grid(MTOT / (64 * NTILES), 4);    // (32, 4)
    // pass 1: x = a, h = ev  -> h1 (fp32 + bf16 splits into fresh buffers)
    gru_pass_kernel<<<grid, 512, SMEM_TOT>>>(
        xhi_p, xlo_p, hhi_p, hlo_p, h32_p,
        wihh_p, wihl_p, whhh_p, whhl_p, b_ih, b_hh,
        h232_p, h2hi_p, h2lo_p);
    // pass 2: x = h = h1 -> d_out
    gru_pass_kernel<<<grid, 512, SMEM_TOT>>>(
        h2hi_p, h2lo_p, h2hi_p, h2lo_p, h232_p,
        wihh_p, wihl_p, whhh_p, whhl_p, b_ih, b_hh,
        out, nullptr, nullptr);
}

// round 8
// speedup vs baseline: 1.5263x; 1.1999x over previous
#include <cuda_runtime.h>
#include <cuda_bf16.h>
#include <cstdint>

#define B_    256
#define NI    64
#define L_    128
#define H_    128
#define K_    40
#define MTOT  (B_ * K_)          /* 10240 rows */
#define GATES 384

typedef unsigned long long ull;

// ---------------------------------------------------------------------------
// Device scratch
// ---------------------------------------------------------------------------
__device__ __align__(256) __nv_bfloat16 g_xhi[MTOT * H_];
__device__ __align__(256) __nv_bfloat16 g_xlo[MTOT * H_];
__device__ __align__(256) __nv_bfloat16 g_hhi[MTOT * H_];
__device__ __align__(256) __nv_bfloat16 g_hlo[MTOT * H_];
__device__ __align__(256) float         g_h32[MTOT * H_];
__device__ __align__(256) __nv_bfloat16 g_h2hi[MTOT * H_];
__device__ __align__(256) __nv_bfloat16 g_h2lo[MTOT * H_];
__device__ __align__(256) float         g_h232[MTOT * H_];
__device__ __align__(256) __nv_bfloat16 g_wih_hi[GATES * H_];
__device__ __align__(256) __nv_bfloat16 g_wih_lo[GATES * H_];
__device__ __align__(256) __nv_bfloat16 g_whh_hi[GATES * H_];
__device__ __align__(256) __nv_bfloat16 g_whh_lo[GATES * H_];

// ---------------------------------------------------------------------------
// Helpers
// ---------------------------------------------------------------------------
__device__ __forceinline__ uint32_t smem_u32(const void* p) {
    uint32_t a;
    asm("{ .reg .u64 t; cvta.to.shared.u64 t, %1; cvt.u32.u64 %0, t; }"
        : "=r"(a) : "l"(p));
    return a;
}
__device__ __forceinline__ void cp16(uint32_t dst, const void* src) {
    asm volatile("cp.async.cg.shared.global [%0], [%1], 16;"
                 :: "r"(dst), "l"(src) : "memory");
}
#define CP_COMMIT() asm volatile("cp.async.commit_group;" ::: "memory")
#define CP_WAIT0()  asm volatile("cp.async.wait_group 0;" ::: "memory")
#define NB(id)      asm volatile("bar.sync %0, 128;" :: "r"((id) + 1) : "memory")

__device__ __forceinline__ void ldm4(uint32_t* a, uint32_t addr) {
    asm volatile("ldmatrix.sync.aligned.m8n8.x4.shared.b16 {%0,%1,%2,%3}, [%4];"
                 : "=r"(a[0]), "=r"(a[1]), "=r"(a[2]), "=r"(a[3]) : "r"(addr));
}
__device__ __forceinline__ float ldsf(uint32_t addr) {
    float v; asm volatile("ld.shared.f32 %0, [%1];" : "=f"(v) : "r"(addr));
    return v;
}
__device__ __forceinline__ void sts2(uint32_t addr, float a, float b) {
    asm volatile("st.shared.v2.f32 [%0], {%1,%2};"
                 :: "r"(addr), "f"(a), "f"(b) : "memory");
}
__device__ __forceinline__ void hmma(float* c, const uint32_t* a,
                                     uint32_t b0, uint32_t b1) {
    asm volatile("mma.sync.aligned.m16n8k16.row.col.f32.bf16.bf16.f32 "
                 "{%0,%1,%2,%3}, {%4,%5,%6,%7}, {%8,%9}, {%0,%1,%2,%3};"
                 : "+f"(c[0]), "+f"(c[1]), "+f"(c[2]), "+f"(c[3])
                 : "r"(a[0]), "r"(a[1]), "r"(a[2]), "r"(a[3]),
                   "r"(b0), "r"(b1));
}

__device__ __forceinline__ ull pk2(float v) {
    ull r; asm("mov.b64 %0, {%1, %1};" : "=l"(r) : "f"(v)); return r;
}
__device__ __forceinline__ float2 upk(ull v) {
    float2 f; asm("mov.b64 {%0, %1}, %2;" : "=f"(f.x), "=f"(f.y) : "l"(v)); return f;
}
__device__ __forceinline__ void fma2(ull& d, ull a, ull b) {
    asm("fma.rn.f32x2 %0, %1, %2, %0;" : "+l"(d) : "l"(a), "l"(b));
}
__device__ __forceinline__ ull ld2(const float* p) { return *(const ull*)p; }

__device__ __forceinline__ float sigm(float x) {
    return __fdividef(1.0f, 1.0f + __expf(-x));
}
__device__ __forceinline__ float tanh_(float x) {
    return __fdividef(2.0f, 1.0f + __expf(-2.0f * x)) - 1.0f;
}
__device__ __forceinline__ void split_store(float v, __nv_bfloat16* hi,
                                            __nv_bfloat16* lo, int idx) {
    __nv_bfloat16 h = __float2bfloat16(v);
    hi[idx] = h;
    lo[idx] = __float2bfloat16(v - __bfloat162float(h));
}

// ---------------------------------------------------------------------------
// K1: split weights into bf16 hi/lo
// ---------------------------------------------------------------------------
__global__ void prep_kernel(const float* __restrict__ w_ih,
                            const float* __restrict__ w_hh) {
    int idx = blockIdx.x * blockDim.x + threadIdx.x;
    if (idx < GATES * H_) {
        split_store(w_ih[idx], g_wih_hi, g_wih_lo, idx);
        split_store(w_hh[idx], g_whh_hi, g_whh_lo, idx);
    }
}

// ---------------------------------------------------------------------------
// K2: gather + adj GEMM -> x (a) splits, h (ev) splits + fp32 hold.
// ---------------------------------------------------------------------------
__global__ __launch_bounds__(256, 1)
void gather_adj_kernel(const float* __restrict__ seq_out,
                       const int*   __restrict__ target_idxs,
                       const int*   __restrict__ nid2rows,
                       const int*   __restrict__ ev_nids,
                       const float* __restrict__ adj,
                       const float* __restrict__ adj_bias) {
    __shared__ float s_h[K_ * H_];
    __shared__ float s_adj[K_ * K_];

    const int b    = blockIdx.x;
    const int tid  = threadIdx.x;
    const int warp = tid >> 5;
    const int lane = tid & 31;
    const int r0   = warp * 5;
    const int c0   = lane * 2;
    const int c1   = lane * 2 + 64;

    for (int i = tid; i < K_ * K_; i += 256)
        s_adj[i] = adj[b * K_ * K_ + i];

    #pragma unroll
    for (int rr = 0; rr < 5; rr++) {
        int k   = r0 + rr;
        int nid = ev_nids[b * K_ + k];
        int row = nid2rows[b * NI + nid];
        long long gi = (long long)b * NI + row;
        int t = target_idxs[gi];
        const float4* src = reinterpret_cast<const float4*>(
            seq_out + (gi * L_ + t) * (long long)H_);
        reinterpret_cast<float4*>(s_h + k * H_)[lane] = src[lane];
    }
    __syncthreads();

    ull bias0 = ld2(adj_bias + c0);
    ull bias1 = ld2(adj_bias + c1);
    ull acc[5][2];
    #pragma unroll
    for (int r = 0; r < 5; r++) { acc[r][0] = bias0; acc[r][1] = bias1; }

    for (int i = 0; i < K_; i++) {
        ull e0 = ld2(s_h + i * H_ + c0);
        ull e1 = ld2(s_h + i * H_ + c1);
        #pragma unroll
        for (int r = 0; r < 5; r++) {
            ull av = pk2(s_adj[i * K_ + r0 + r]);
            fma2(acc[r][0], av, e0);
            fma2(acc[r][1], av, e1);
        }
    }

    #pragma unroll
    for (int r = 0; r < 5; r++) {
        int gr = b * K_ + r0 + r;
        float2 a0 = upk(acc[r][0]);
        float2 a1 = upk(acc[r][1]);
        split_store(a0.x, g_xhi, g_xlo, gr * H_ + c0);
        split_store(a0.y, g_xhi, g_xlo, gr * H_ + c0 + 1);
        split_store(a1.x, g_xhi, g_xlo, gr * H_ + c1);
        split_store(a1.y, g_xhi, g_xlo, gr * H_ + c1 + 1);

        float2 e0 = upk(ld2(s_h + (r0 + r) * H_ + c0));
        float2 e1 = upk(ld2(s_h + (r0 + r) * H_ + c1));
        g_h32[gr * H_ + c0]     = e0.x;
        g_h32[gr * H_ + c0 + 1] = e0.y;
        g_h32[gr * H_ + c1]     = e1.x;
        g_h32[gr * H_ + c1 + 1] = e1.y;
        split_store(e0.x, g_hhi, g_hlo, gr * H_ + c0);
        split_store(e0.y, g_hhi, g_hlo, gr * H_ + c0 + 1);
        split_store(e1.x, g_hhi, g_hlo, gr * H_ + c1);
        split_store(e1.y, g_hhi, g_hlo, gr * H_ + c1 + 1);
    }
}

// ---------------------------------------------------------------------------
// K3: one GRU pass via HMMA, persistent-W, register-resident whi fragments.
// Grid (32, 4), 256 threads = 8 warps = 2 row-groups (32 rows) x 4 chunks.
// Warp tile m32 x n48; whi B-fragments live in registers across all 5 tiles
// (loaded once, 96 regs); xhi A-fragments reused across terms 1+2.
// LDSM per warp per tile: 32 A + 24 wlo = 56 (was 2x96).
// ---------------------------------------------------------------------------
#define PITCH    272                      /* bytes per A/W smem row */
#define A_TSZ    (64 * PITCH)             /* 17408 */
#define SW_OFF   (4 * A_TSZ)              /* 69632 */
#define W_TSZ    (192 * PITCH)            /* 52224 */
#define SG_OFF   (SW_OFF + 2 * W_TSZ)     /* 174080 */
#define GPITCH   784                      /* 196 f32 words per gate row */
#define SMEM_TOT (SG_OFF + 64 * GPITCH)   /* 224256 */
#define NTILES   5

__global__ __launch_bounds__(256, 1)
void gru_pass_kernel(const __nv_bfloat16* __restrict__ xhi,
                     const __nv_bfloat16* __restrict__ xlo,
                     const __nv_bfloat16* __restrict__ hhi,
                     const __nv_bfloat16* __restrict__ hlo,
                     const float* __restrict__ hold,
                     const __nv_bfloat16* __restrict__ wih_hi,
                     const __nv_bfloat16* __restrict__ wih_lo,
                     const __nv_bfloat16* __restrict__ whh_hi,
                     const __nv_bfloat16* __restrict__ whh_lo,
                     const float* __restrict__ b_ih,
                     const float* __restrict__ b_hh,
                     float* __restrict__ out32,
                     __nv_bfloat16* __restrict__ out_hi,
                     __nv_bfloat16* __restrict__ out_lo) {
    extern __shared__ __align__(16) char smem[];
    const uint32_t sb  = smem_u32(smem);
    const int tid   = threadIdx.x;
    const int wid   = tid >> 5;
    const int lane  = tid & 31;
    const int ycol0 = blockIdx.y * 32;
    const int m0    = blockIdx.x * NTILES;      // first M-tile

    const int chunk = wid >> 1;            // 0..3 gate-col chunk (48 cols)
    const int rowg  = wid & 1;             // 0..1 row group (32 rows)
    const int side  = chunk >> 1;          // 0: gi (x), 1: gh (h)
    const int mrows = rowg * 32;
    const int gt    = chunk * 32 + lane;   // group-local tid 0..127

    // ---- per-group A slice prefetch (32 rows of xhi, xlo, hhi, hlo) --------
    const __nv_bfloat16* asrc[4] = {xhi, xlo, hhi, hlo};
    auto loadA = [&](int m) {
        #pragma unroll
        for (int t4 = 0; t4 < 4; t4++) {
            const __nv_bfloat16* src = asrc[t4]
                + ((size_t)m * 64 + mrows) * H_;
            uint32_t dst = sb + t4 * A_TSZ + mrows * PITCH;
            #pragma unroll
            for (int c = gt; c < 512; c += 128) {       // 32 rows x 16 chunks
                int row = c >> 4, cw = c & 15;
                cp16(dst + row * PITCH + cw * 16, src + row * H_ + cw * 8);
            }
        }
    };

    // ---- W load (once): 192 gate-rows x 128 k, hi then lo ------------------
    {
        const __nv_bfloat16* wsrc[4] = {wih_hi, whh_hi, wih_lo, whh_lo};
        #pragma unroll
        for (int part = 0; part < 2; part++) {
            uint32_t dst = sb + SW_OFF + part * W_TSZ;
            #pragma unroll
            for (int c = tid; c < 3072; c += 256) {     // 192 rows x 16 chunks
                int gp = c >> 4, cw = c & 15;
                int sde = gp / 96, rem = gp % 96;
                int gate = rem >> 5, hc = rem & 31;
                const __nv_bfloat16* src = wsrc[part * 2 + sde]
                    + (size_t)(gate * H_ + ycol0 + hc) * H_ + cw * 8;
                cp16(dst + gp * PITCH + cw * 16, src);
            }
        }
    }
    loadA(m0);
    CP_COMMIT();
    CP_WAIT0();
    __syncthreads();                       // W + first A visible to all

    // ---- tiling constants ---------------------------------------------------
    const uint32_t a_lanoff = (uint32_t)(lane & 15) * PITCH
                            + ((lane >> 4) & 1) * 16;
    const uint32_t b_lanoff =
        (uint32_t)(chunk * 48 + (lane & 7) + ((lane >> 4) << 3)) * PITCH
        + ((lane >> 3) & 1) * 16;

    // ---- whi B-fragments: load once, keep in registers ---------------------
    uint32_t bw[8][3][4];
    {
        const uint32_t Bhi = sb + SW_OFF + b_lanoff;
        #pragma unroll
        for (int ks = 0; ks < 8; ks++)
            #pragma unroll
            for (int j2 = 0; j2 < 3; j2++)
                ldm4(bw[ks][j2], Bhi + j2 * (16 * PITCH) + ks * 32);
    }

    // epilogue constants: group (128 thr) handles its own 32 rows x 32 cols
    const int e_col = ycol0 + lane;
    const float bir = b_ih[e_col],       bhr = b_hh[e_col];
    const float biz = b_ih[128 + e_col], bhz = b_hh[128 + e_col];
    const float bin = b_ih[256 + e_col], bhn = b_hh[256 + e_col];

    #pragma unroll 1
    for (int it = 0; it < NTILES; it++) {
        const int m     = m0 + it;
        const int mrow0 = m * 64;

        // ---- MMA compute: m32 x n48, 3 emulation terms -------------------------
        float acc[2][6][4];
        #pragma unroll
        for (int mt = 0; mt < 2; mt++)
            #pragma unroll
            for (int j = 0; j < 6; j++)
                #pragma unroll
                for (int q = 0; q < 4; q++) acc[mt][j][q] = 0.0f;

        const uint32_t Axhi = sb + (side * 2 + 0) * A_TSZ + mrows * PITCH + a_lanoff;
        const uint32_t Axlo = sb + (side * 2 + 1) * A_TSZ + mrows * PITCH + a_lanoff;
        const uint32_t Blo  = sb + SW_OFF + W_TSZ + b_lanoff;

        #pragma unroll
        for (int ks = 0; ks < 8; ks++) {
            uint32_t a0[4], a1[4];
            ldm4(a0, Axhi + ks * 32);
            ldm4(a1, Axhi + ks * 32 + 16 * PITCH);
            // term 1: xhi * whi (B resident)
            #pragma unroll
            for (int j2 = 0; j2 < 3; j2++) {
                hmma(acc[0][2 * j2],     a0, bw[ks][j2][0], bw[ks][j2][1]);
                hmma(acc[0][2 * j2 + 1], a0, bw[ks][j2][2], bw[ks][j2][3]);
                hmma(acc[1][2 * j2],     a1, bw[ks][j2][0], bw[ks][j2][1]);
                hmma(acc[1][2 * j2 + 1], a1, bw[ks][j2][2], bw[ks][j2][3]);
            }
            // term 2: xhi * wlo (B streamed, A reused)
            #pragma unroll
            for (int j2 = 0; j2 < 3; j2++) {
                uint32_t bl[4];
                ldm4(bl, Blo + j2 * (16 * PITCH) + ks * 32);
                hmma(acc[0][2 * j2],     a0, bl[0], bl[1]);
                hmma(acc[0][2 * j2 + 1], a0, bl[2], bl[3]);
                hmma(acc[1][2 * j2],     a1, bl[0], bl[1]);
                hmma(acc[1][2 * j2 + 1], a1, bl[2], bl[3]);
            }
            // term 3: xlo * whi (B resident)
            uint32_t l0[4], l1[4];
            ldm4(l0, Axlo + ks * 32);
            ldm4(l1, Axlo + ks * 32 + 16 * PITCH);
            #pragma unroll
            for (int j2 = 0; j2 < 3; j2++) {
                hmma(acc[0][2 * j2],     l0, bw[ks][j2][0], bw[ks][j2][1]);
                hmma(acc[0][2 * j2 + 1], l0, bw[ks][j2][2], bw[ks][j2][3]);
                hmma(acc[1][2 * j2],     l1, bw[ks][j2][0], bw[ks][j2][1]);
                hmma(acc[1][2 * j2 + 1], l1, bw[ks][j2][2], bw[ks][j2][3]);
            }
        }
        NB(rowg);                          // group's A slice consumed, G free

        // ---- prefetch next A slice (overlaps dump + epilogue) ------------------
        if (it + 1 < NTILES) { loadA(m + 1); CP_COMMIT(); }

        // ---- dump gates to smem G (group's 32 rows) ----------------------------
        #pragma unroll
        for (int mt = 0; mt < 2; mt++) {
            int row = mrows + mt * 16 + (lane >> 2);
            #pragma unroll
            for (int j = 0; j < 6; j++) {
                int col = chunk * 48 + j * 8 + 2 * (lane & 3);
                uint32_t ad = sb + SG_OFF + row * GPITCH + col * 4;
                sts2(ad,              acc[mt][j][0], acc[mt][j][1]);
                sts2(ad + 8 * GPITCH, acc[mt][j][2], acc[mt][j][3]);
            }
        }
        NB(rowg);                          // G visible within group

        // ---- epilogue: combine gates -> h' (8 rows per thread) -----------------
        #pragma unroll
        for (int rr = 0; rr < 8; rr++) {
            int row = mrows + chunk * 8 + rr;
            uint32_t base = sb + SG_OFF + row * GPITCH + lane * 4;
            float gir = ldsf(base);
            float giz = ldsf(base + 32 * 4);
            float gin = ldsf(base + 64 * 4);
            float ghr = ldsf(base + 96 * 4);
            float ghz = ldsf(base + 128 * 4);
            float ghn = ldsf(base + 160 * 4);
            float r = sigm(gir + bir + ghr + bhr);
            float z = sigm(giz + biz + ghz + bhz);
            float n = tanh_(gin + bin + r * (ghn + bhn));
            long long idx = (long long)(mrow0 + row) * H_ + e_col;
            float ho = hold[idx];
            float hn = (1.0f - z) * n + z * ho;
            out32[idx] = hn;
            if (out_hi) split_store(hn, out_hi, out_lo, (int)idx);
        }

        if (it + 1 < NTILES) { CP_WAIT0(); }
        NB(rowg);                          // next A ready / G reuse safe
    }
}

// ---------------------------------------------------------------------------
extern "C" void kernel_launch(void* const* d_in, const int* in_sizes, int n_in,
                              void* d_out, int out_size) {
    const float* seq_out     = (const float*)d_in[0];
    const int*   target_idxs = (const int*)  d_in[1];
    const int*   nid2rows    = (const int*)  d_in[2];
    const int*   ev_nids     = (const int*)  d_in[3];
    const float* adj         = (const float*)d_in[4];
    const float* adj_bias    = (const float*)d_in[5];
    const float* w_ih        = (const float*)d_in[6];
    const float* w_hh        = (const float*)d_in[7];
    const float* b_ih        = (const float*)d_in[8];
    const float* b_hh        = (const float*)d_in[9];
    float* out = (float*)d_out;

    static bool attr_set = false;
    if (!attr_set) {
        cudaFuncSetAttribute(gru_pass_kernel,
                             cudaFuncAttributeMaxDynamicSharedMemorySize,
                             SMEM_TOT);
        attr_set = true;
    }

    prep_kernel<<<(GATES * H_ + 255) / 256, 256>>>(w_ih, w_hh);
    gather_adj_kernel<<<B_, 256>>>(seq_out, target_idxs, nid2rows, ev_nids,
                                   adj, adj_bias);

    __nv_bfloat16 *xhi_p, *xlo_p, *hhi_p, *hlo_p, *h2hi_p, *h2lo_p;
    __nv_bfloat16 *wihh_p, *wihl_p, *whhh_p, *whhl_p;
    float *h32_p, *h232_p;
    cudaGetSymbolAddress((void**)&xhi_p,  g_xhi);
    cudaGetSymbolAddress((void**)&xlo_p,  g_xlo);
    cudaGetSymbolAddress((void**)&hhi_p,  g_hhi);
    cudaGetSymbolAddress((void**)&hlo_p,  g_hlo);
    cudaGetSymbolAddress((void**)&h2hi_p, g_h2hi);
    cudaGetSymbolAddress((void**)&h2lo_p, g_h2lo);
    cudaGetSymbolAddress((void**)&h32_p,  g_h32);
    cudaGetSymbolAddress((void**)&h232_p, g_h232);
    cudaGetSymbolAddress((void**)&wihh_p, g_wih_hi);
    cudaGetSymbolAddress((void**)&wihl_p, g_wih_lo);
    cudaGetSymbolAddress((void**)&whhh_p, g_whh_hi);
    cudaGetSymbolAddress((void**)&whhl_p, g_whh_lo);

    dim3 grid(MTOT / (64 * NTILES), 4);    // (32, 4)
    // pass 1: x = a, h = ev  -> h1 (fp32 + bf16 splits into fresh buffers)
    gru_pass_kernel<<<grid, 256, SMEM_TOT>>>(
        xhi_p, xlo_p, hhi_p, hlo_p, h32_p,
        wihh_p, wihl_p, whhh_p, whhl_p, b_ih, b_hh,
        h232_p, h2hi_p, h2lo_p);
    // pass 2: x = h = h1 -> d_out
    gru_pass_kernel<<<grid, 256, SMEM_TOT>>>(
        h2hi_p, h2lo_p, h2hi_p, h2lo_p, h232_p,
        wihh_p, wihl_p, whhh_p, whhl_p, b_ih, b_hh,
        out, nullptr, nullptr);
}

// round 9
// speedup vs baseline: 1.6025x; 1.0499x over previous
#include <cuda_runtime.h>
#include <cuda_bf16.h>
#include <cstdint>

#define B_    256
#define NI    64
#define L_    128
#define H_    128
#define K_    40
#define MTOT  (B_ * K_)          /* 10240 rows */
#define GATES 384

typedef unsigned long long ull;

// ---------------------------------------------------------------------------
// Device scratch
// ---------------------------------------------------------------------------
__device__ __align__(256) __nv_bfloat16 g_xhi[MTOT * H_];
__device__ __align__(256) __nv_bfloat16 g_xlo[MTOT * H_];
__device__ __align__(256) __nv_bfloat16 g_hhi[MTOT * H_];
__device__ __align__(256) __nv_bfloat16 g_hlo[MTOT * H_];
__device__ __align__(256) float         g_h32[MTOT * H_];
__device__ __align__(256) __nv_bfloat16 g_h2hi[MTOT * H_];
__device__ __align__(256) __nv_bfloat16 g_h2lo[MTOT * H_];
__device__ __align__(256) float         g_h232[MTOT * H_];
__device__ __align__(256) __nv_bfloat16 g_wih_hi[GATES * H_];
__device__ __align__(256) __nv_bfloat16 g_wih_lo[GATES * H_];
__device__ __align__(256) __nv_bfloat16 g_whh_hi[GATES * H_];
__device__ __align__(256) __nv_bfloat16 g_whh_lo[GATES * H_];

// ---------------------------------------------------------------------------
// Helpers
// ---------------------------------------------------------------------------
__device__ __forceinline__ uint32_t smem_u32(const void* p) {
    uint32_t a;
    asm("{ .reg .u64 t; cvta.to.shared.u64 t, %1; cvt.u32.u64 %0, t; }"
        : "=r"(a) : "l"(p));
    return a;
}
__device__ __forceinline__ void cp16(uint32_t dst, const void* src) {
    asm volatile("cp.async.cg.shared.global [%0], [%1], 16;"
                 :: "r"(dst), "l"(src) : "memory");
}
#define CP_COMMIT() asm volatile("cp.async.commit_group;" ::: "memory")
#define CP_WAIT0()  asm volatile("cp.async.wait_group 0;" ::: "memory")
#define NB(id)      asm volatile("bar.sync %0, 128;" :: "r"((id) + 1) : "memory")

__device__ __forceinline__ void ldm4(uint32_t* a, uint32_t addr) {
    asm volatile("ldmatrix.sync.aligned.m8n8.x4.shared.b16 {%0,%1,%2,%3}, [%4];"
                 : "=r"(a[0]), "=r"(a[1]), "=r"(a[2]), "=r"(a[3]) : "r"(addr));
}
__device__ __forceinline__ void ldm2(uint32_t* a, uint32_t addr) {
    asm volatile("ldmatrix.sync.aligned.m8n8.x2.shared.b16 {%0,%1}, [%2];"
                 : "=r"(a[0]), "=r"(a[1]) : "r"(addr));
}
__device__ __forceinline__ float2 lds2f(uint32_t addr) {
    float2 v;
    asm volatile("ld.shared.v2.f32 {%0,%1}, [%2];"
                 : "=f"(v.x), "=f"(v.y) : "r"(addr));
    return v;
}
__device__ __forceinline__ void hmma(float* c, const uint32_t* a,
                                     uint32_t b0, uint32_t b1) {
    asm volatile("mma.sync.aligned.m16n8k16.row.col.f32.bf16.bf16.f32 "
                 "{%0,%1,%2,%3}, {%4,%5,%6,%7}, {%8,%9}, {%0,%1,%2,%3};"
                 : "+f"(c[0]), "+f"(c[1]), "+f"(c[2]), "+f"(c[3])
                 : "r"(a[0]), "r"(a[1]), "r"(a[2]), "r"(a[3]),
                   "r"(b0), "r"(b1));
}

__device__ __forceinline__ ull pk2(float v) {
    ull r; asm("mov.b64 %0, {%1, %1};" : "=l"(r) : "f"(v)); return r;
}
__device__ __forceinline__ float2 upk(ull v) {
    float2 f; asm("mov.b64 {%0, %1}, %2;" : "=f"(f.x), "=f"(f.y) : "l"(v)); return f;
}
__device__ __forceinline__ void fma2(ull& d, ull a, ull b) {
    asm("fma.rn.f32x2 %0, %1, %2, %0;" : "+l"(d) : "l"(a), "l"(b));
}
__device__ __forceinline__ ull ld2(const float* p) { return *(const ull*)p; }

__device__ __forceinline__ float sigm(float x) {
    return __fdividef(1.0f, 1.0f + __expf(-x));
}
__device__ __forceinline__ float tanh_(float x) {
    return __fdividef(2.0f, 1.0f + __expf(-2.0f * x)) - 1.0f;
}
__device__ __forceinline__ void split_store(float v, __nv_bfloat16* hi,
                                            __nv_bfloat16* lo, int idx) {
    __nv_bfloat16 h = __float2bfloat16(v);
    hi[idx] = h;
    lo[idx] = __float2bfloat16(v - __bfloat162float(h));
}
// pack two floats into bf16x2 (lo = a, hi = b)
__device__ __forceinline__ uint32_t bf16x2_of(float a, float b) {
    uint32_t r;
    asm("cvt.rn.bf16x2.f32 %0, %1, %2;" : "=r"(r) : "f"(b), "f"(a));
    return r;
}

// ---------------------------------------------------------------------------
// K1: split weights into bf16 hi/lo
// ---------------------------------------------------------------------------
__global__ void prep_kernel(const float* __restrict__ w_ih,
                            const float* __restrict__ w_hh) {
    int idx = blockIdx.x * blockDim.x + threadIdx.x;
    if (idx < GATES * H_) {
        split_store(w_ih[idx], g_wih_hi, g_wih_lo, idx);
        split_store(w_hh[idx], g_whh_hi, g_whh_lo, idx);
    }
}

// ---------------------------------------------------------------------------
// K2: gather + adj GEMM -> x (a) splits, h (ev) splits + fp32 hold.
// ---------------------------------------------------------------------------
__global__ __launch_bounds__(256, 1)
void gather_adj_kernel(const float* __restrict__ seq_out,
                       const int*   __restrict__ target_idxs,
                       const int*   __restrict__ nid2rows,
                       const int*   __restrict__ ev_nids,
                       const float* __restrict__ adj,
                       const float* __restrict__ adj_bias) {
    __shared__ float s_h[K_ * H_];
    __shared__ float s_adj[K_ * K_];

    const int b    = blockIdx.x;
    const int tid  = threadIdx.x;
    const int warp = tid >> 5;
    const int lane = tid & 31;
    const int r0   = warp * 5;
    const int c0   = lane * 2;
    const int c1   = lane * 2 + 64;

    for (int i = tid; i < K_ * K_; i += 256)
        s_adj[i] = adj[b * K_ * K_ + i];

    #pragma unroll
    for (int rr = 0; rr < 5; rr++) {
        int k   = r0 + rr;
        int nid = ev_nids[b * K_ + k];
        int row = nid2rows[b * NI + nid];
        long long gi = (long long)b * NI + row;
        int t = target_idxs[gi];
        const float4* src = reinterpret_cast<const float4*>(
            seq_out + (gi * L_ + t) * (long long)H_);
        reinterpret_cast<float4*>(s_h + k * H_)[lane] = src[lane];
    }
    __syncthreads();

    ull bias0 = ld2(adj_bias + c0);
    ull bias1 = ld2(adj_bias + c1);
    ull acc[5][2];
    #pragma unroll
    for (int r = 0; r < 5; r++) { acc[r][0] = bias0; acc[r][1] = bias1; }

    for (int i = 0; i < K_; i++) {
        ull e0 = ld2(s_h + i * H_ + c0);
        ull e1 = ld2(s_h + i * H_ + c1);
        #pragma unroll
        for (int r = 0; r < 5; r++) {
            ull av = pk2(s_adj[i * K_ + r0 + r]);
            fma2(acc[r][0], av, e0);
            fma2(acc[r][1], av, e1);
        }
    }

    #pragma unroll
    for (int r = 0; r < 5; r++) {
        int gr = b * K_ + r0 + r;
        float2 a0 = upk(acc[r][0]);
        float2 a1 = upk(acc[r][1]);
        split_store(a0.x, g_xhi, g_xlo, gr * H_ + c0);
        split_store(a0.y, g_xhi, g_xlo, gr * H_ + c0 + 1);
        split_store(a1.x, g_xhi, g_xlo, gr * H_ + c1);
        split_store(a1.y, g_xhi, g_xlo, gr * H_ + c1 + 1);

        float2 e0 = upk(ld2(s_h + (r0 + r) * H_ + c0));
        float2 e1 = upk(ld2(s_h + (r0 + r) * H_ + c1));
        g_h32[gr * H_ + c0]     = e0.x;
        g_h32[gr * H_ + c0 + 1] = e0.y;
        g_h32[gr * H_ + c1]     = e1.x;
        g_h32[gr * H_ + c1 + 1] = e1.y;
        split_store(e0.x, g_hhi, g_hlo, gr * H_ + c0);
        split_store(e0.y, g_hhi, g_hlo, gr * H_ + c0 + 1);
        split_store(e1.x, g_hhi, g_hlo, gr * H_ + c1);
        split_store(e1.y, g_hhi, g_hlo, gr * H_ + c1 + 1);
    }
}

// ---------------------------------------------------------------------------
// K3: one GRU pass via HMMA; all 6 gate blocks per warp -> register epilogue.
// Grid (32, 4), 256 threads = 8 warps = 4 col-groups (8 h-cols) x 2 row-groups
// (32 rows).  Warp computes ih_r/z/n + hh_r/z/n for its rows x cols; the GRU
// combine is pure register math (no gate smem exchange).  whi+whh_hi fragments
// register-resident (96 regs); wlo streamed (ldmatrix.x2); hold prefetched to
// double-buffered smem with the A cp.async.
// ---------------------------------------------------------------------------
#define PITCH    272                      /* bytes per A/W smem row */
#define A_TSZ    (64 * PITCH)             /* 17408 */
#define SW_OFF   (4 * A_TSZ)              /* 69632 */
#define W_TSZ    (192 * PITCH)            /* 52224 */
#define HOLD_OFF (SW_OFF + 2 * W_TSZ)     /* 174080 */
#define HPITCHB  144                      /* 36 floats, 16B aligned rows */
#define HOLD_SZ  (64 * HPITCHB)           /* 9216 */
#define SMEM_TOT (HOLD_OFF + 2 * HOLD_SZ) /* 192512 */
#define NTILES   5

__global__ __launch_bounds__(256, 1)
void gru_pass_kernel(const __nv_bfloat16* __restrict__ xhi,
                     const __nv_bfloat16* __restrict__ xlo,
                     const __nv_bfloat16* __restrict__ hhi,
                     const __nv_bfloat16* __restrict__ hlo,
                     const float* __restrict__ hold,
                     const __nv_bfloat16* __restrict__ wih_hi,
                     const __nv_bfloat16* __restrict__ wih_lo,
                     const __nv_bfloat16* __restrict__ whh_hi,
                     const __nv_bfloat16* __restrict__ whh_lo,
                     const float* __restrict__ b_ih,
                     const float* __restrict__ b_hh,
                     float* __restrict__ out32,
                     __nv_bfloat16* __restrict__ out_hi,
                     __nv_bfloat16* __restrict__ out_lo) {
    extern __shared__ __align__(16) char smem[];
    const uint32_t sb  = smem_u32(smem);
    const int tid   = threadIdx.x;
    const int wid   = tid >> 5;
    const int lane  = tid & 31;
    const int ycol0 = blockIdx.y * 32;
    const int m0    = blockIdx.x * NTILES;      // first M-tile

    const int cg    = wid >> 1;            // 0..3 col group (8 h-cols)
    const int rowg  = wid & 1;             // 0..1 row group (32 rows)
    const int mrows = rowg * 32;
    const int gt    = cg * 32 + lane;      // group-local tid 0..127

    // ---- per-group prefetch: A slices (xhi,xlo,hhi,hlo) + hold -------------
    const __nv_bfloat16* asrc[4] = {xhi, xlo, hhi, hlo};
    auto loadA = [&](int m, int pb) {
        #pragma unroll
        for (int t4 = 0; t4 < 4; t4++) {
            const __nv_bfloat16* src = asrc[t4]
                + ((size_t)m * 64 + mrows) * H_;
            uint32_t dst = sb + t4 * A_TSZ + mrows * PITCH;
            #pragma unroll
            for (int c = gt; c < 512; c += 128) {       // 32 rows x 16 chunks
                int row = c >> 4, cw = c & 15;
                cp16(dst + row * PITCH + cw * 16, src + row * H_ + cw * 8);
            }
        }
        // hold slice: 32 rows x 32 cols f32 (8 chunks/row)
        {
            const float* src = hold + ((size_t)m * 64 + mrows) * H_ + ycol0;
            uint32_t dst = sb + HOLD_OFF + pb * HOLD_SZ + mrows * HPITCHB;
            #pragma unroll
            for (int c = gt; c < 256; c += 128) {       // 32 rows x 8 chunks
                int row = c >> 3, cw = c & 7;
                cp16(dst + row * HPITCHB + cw * 16, src + row * H_ + cw * 4);
            }
        }
    };

    // ---- W load (once): 192 gate-rows x 128 k, hi then lo ------------------
    {
        const __nv_bfloat16* wsrc[4] = {wih_hi, whh_hi, wih_lo, whh_lo};
        #pragma unroll
        for (int part = 0; part < 2; part++) {
            uint32_t dst = sb + SW_OFF + part * W_TSZ;
            #pragma unroll
            for (int c = tid; c < 3072; c += 256) {     // 192 rows x 16 chunks
                int gp = c >> 4, cw = c & 15;
                int sde = gp / 96, rem = gp % 96;
                int gate = rem >> 5, hc = rem & 31;
                const __nv_bfloat16* src = wsrc[part * 2 + sde]
                    + (size_t)(gate * H_ + ycol0 + hc) * H_ + cw * 8;
                cp16(dst + gp * PITCH + cw * 16, src);
            }
        }
    }
    loadA(m0, 0);
    CP_COMMIT();
    CP_WAIT0();
    __syncthreads();                       // W + first A/hold visible

    // ---- fragment address constants -----------------------------------------
    const uint32_t a_lanoff = (uint32_t)(lane & 15) * PITCH
                            + ((lane >> 4) & 1) * 16;
    const int l15 = lane & 15;
    const uint32_t b_lanoff = (uint32_t)(l15 & 7) * PITCH + (l15 >> 3) * 16;

    // W row offset per gate block (0..2: ih r/z/n, 3..5: hh r/z/n)
    uint32_t wrow_off[6];
    #pragma unroll
    for (int blk = 0; blk < 6; blk++) {
        int sde = blk / 3, gate = blk % 3;
        wrow_off[blk] = (uint32_t)(sde * 96 + gate * 32 + cg * 8) * PITCH
                      + b_lanoff;
    }

    // ---- resident hi-weight fragments (96 regs) -----------------------------
    uint32_t bw[8][6][2];
    #pragma unroll
    for (int ks = 0; ks < 8; ks++)
        #pragma unroll
        for (int blk = 0; blk < 6; blk++)
            ldm2(bw[ks][blk], sb + SW_OFF + wrow_off[blk] + ks * 32);

    // ---- epilogue constants (biases hoisted) ---------------------------------
    const int e_colp = ycol0 + cg * 8 + (lane & 3) * 2;   // even col pair base
    const float2 BIr = *(const float2*)(b_ih + e_colp);
    const float2 BIz = *(const float2*)(b_ih + 128 + e_colp);
    const float2 BIn = *(const float2*)(b_ih + 256 + e_colp);
    const float2 BHr = *(const float2*)(b_hh + e_colp);
    const float2 BHz = *(const float2*)(b_hh + 128 + e_colp);
    const float2 BHn = *(const float2*)(b_hh + 256 + e_colp);
    const uint32_t h_lanoff = (uint32_t)(cg * 8 + (lane & 3) * 2) * 4;

    int pb = 0;
    #pragma unroll 1
    for (int it = 0; it < NTILES; it++) {
        const int m     = m0 + it;
        const int mrow0 = m * 64;

        // ---- MMA compute: all 6 gate blocks, 3 emulation terms ---------------
        float acc[2][6][4];
        #pragma unroll
        for (int mt = 0; mt < 2; mt++)
            #pragma unroll
            for (int j = 0; j < 6; j++)
                #pragma unroll
                for (int q = 0; q < 4; q++) acc[mt][j][q] = 0.0f;

        const uint32_t Ax0 = sb + 0 * A_TSZ + mrows * PITCH + a_lanoff; // xhi
        const uint32_t Ax1 = sb + 1 * A_TSZ + mrows * PITCH + a_lanoff; // xlo
        const uint32_t Ah0 = sb + 2 * A_TSZ + mrows * PITCH + a_lanoff; // hhi
        const uint32_t Ah1 = sb + 3 * A_TSZ + mrows * PITCH + a_lanoff; // hlo
        const uint32_t Blo = sb + SW_OFF + W_TSZ;

        #pragma unroll
        for (int ks = 0; ks < 8; ks++) {
            uint32_t xh[2][4], xl[2][4], hh[2][4], hl[2][4];
            ldm4(xh[0], Ax0 + ks * 32);
            ldm4(xh[1], Ax0 + ks * 32 + 16 * PITCH);
            ldm4(hh[0], Ah0 + ks * 32);
            ldm4(hh[1], Ah0 + ks * 32 + 16 * PITCH);
            ldm4(xl[0], Ax1 + ks * 32);
            ldm4(xl[1], Ax1 + ks * 32 + 16 * PITCH);
            ldm4(hl[0], Ah1 + ks * 32);
            ldm4(hl[1], Ah1 + ks * 32 + 16 * PITCH);

            #pragma unroll
            for (int blk = 0; blk < 6; blk++) {
                const uint32_t* ahi0 = (blk < 3) ? xh[0] : hh[0];
                const uint32_t* ahi1 = (blk < 3) ? xh[1] : hh[1];
                const uint32_t* alo0 = (blk < 3) ? xl[0] : hl[0];
                const uint32_t* alo1 = (blk < 3) ? xl[1] : hl[1];
                uint32_t w0 = bw[ks][blk][0], w1 = bw[ks][blk][1];
                // term 1: a_hi * w_hi (resident)
                hmma(acc[0][blk], ahi0, w0, w1);
                hmma(acc[1][blk], ahi1, w0, w1);
                // term 2: a_hi * w_lo (streamed)
                uint32_t bl[2];
                ldm2(bl, Blo + wrow_off[blk] + ks * 32);
                hmma(acc[0][blk], ahi0, bl[0], bl[1]);
                hmma(acc[1][blk], ahi1, bl[0], bl[1]);
                // term 3: a_lo * w_hi (resident)
                hmma(acc[0][blk], alo0, w0, w1);
                hmma(acc[1][blk], alo1, w0, w1);
            }
        }
        NB(rowg);                          // group's A slice fully consumed

        // ---- prefetch next A + hold (overlaps epilogue) -----------------------
        if (it + 1 < NTILES) { loadA(m + 1, pb ^ 1); CP_COMMIT(); }

        // ---- register epilogue: combine gates -> h' ---------------------------
        const uint32_t hbase = sb + HOLD_OFF + pb * HOLD_SZ + h_lanoff;
        #pragma unroll
        for (int mt = 0; mt < 2; mt++) {
            #pragma unroll
            for (int half = 0; half < 2; half++) {
                int row  = mrows + mt * 16 + (lane >> 2) + half * 8;
                int q0   = half * 2;
                float2 ho = lds2f(hbase + row * HPITCHB);
                float gir0 = acc[mt][0][q0],     gir1 = acc[mt][0][q0 + 1];
                float giz0 = acc[mt][1][q0],     giz1 = acc[mt][1][q0 + 1];
                float gin0 = acc[mt][2][q0],     gin1 = acc[mt][2][q0 + 1];
                float ghr0 = acc[mt][3][q0],     ghr1 = acc[mt][3][q0 + 1];
                float ghz0 = acc[mt][4][q0],     ghz1 = acc[mt][4][q0 + 1];
                float ghn0 = acc[mt][5][q0],     ghn1 = acc[mt][5][q0 + 1];
                float r0 = sigm(gir0 + BIr.x + ghr0 + BHr.x);
                float r1 = sigm(gir1 + BIr.y + ghr1 + BHr.y);
                float z0 = sigm(giz0 + BIz.x + ghz0 + BHz.x);
                float z1 = sigm(giz1 + BIz.y + ghz1 + BHz.y);
                float n0 = tanh_(gin0 + BIn.x + r0 * (ghn0 + BHn.x));
                float n1 = tanh_(gin1 + BIn.y + r1 * (ghn1 + BHn.y));
                float hn0 = (1.0f - z0) * n0 + z0 * ho.x;
                float hn1 = (1.0f - z1) * n1 + z1 * ho.y;
                long long idx = (long long)(mrow0 + row) * H_ + e_colp;
                *(float2*)(out32 + idx) = make_float2(hn0, hn1);
                if (out_hi) {
                    __nv_bfloat16 h0 = __float2bfloat16(hn0);
                    __nv_bfloat16 h1 = __float2bfloat16(hn1);
                    float l0 = hn0 - __bfloat162float(h0);
                    float l1 = hn1 - __bfloat162float(h1);
                    *(uint32_t*)(out_hi + idx) =
                        bf16x2_of(__bfloat162float(h0), __bfloat162float(h1));
                    *(uint32_t*)(out_lo + idx) = bf16x2_of(l0, l1);
                }
            }
        }

        if (it + 1 < NTILES) { CP_WAIT0(); }
        NB(rowg);                          // next A/hold ready for whole group
        pb ^= 1;
    }
}

// ---------------------------------------------------------------------------
extern "C" void kernel_launch(void* const* d_in, const int* in_sizes, int n_in,
                              void* d_out, int out_size) {
    const float* seq_out     = (const float*)d_in[0];
    const int*   target_idxs = (const int*)  d_in[1];
    const int*   nid2rows    = (const int*)  d_in[2];
    const int*   ev_nids     = (const int*)  d_in[3];
    const float* adj         = (const float*)d_in[4];
    const float* adj_bias    = (const float*)d_in[5];
    const float* w_ih        = (const float*)d_in[6];
    const float* w_hh        = (const float*)d_in[7];
    const float* b_ih        = (const float*)d_in[8];
    const float* b_hh        = (const float*)d_in[9];
    float* out = (float*)d_out;

    static bool attr_set = false;
    if (!attr_set) {
        cudaFuncSetAttribute(gru_pass_kernel,
                             cudaFuncAttributeMaxDynamicSharedMemorySize,
                             SMEM_TOT);
        attr_set = true;
    }

    prep_kernel<<<(GATES * H_ + 255) / 256, 256>>>(w_ih, w_hh);
    gather_adj_kernel<<<B_, 256>>>(seq_out, target_idxs, nid2rows, ev_nids,
                                   adj, adj_bias);

    __nv_bfloat16 *xhi_p, *xlo_p, *hhi_p, *hlo_p, *h2hi_p, *h2lo_p;
    __nv_bfloat16 *wihh_p, *wihl_p, *whhh_p, *whhl_p;
    float *h32_p, *h232_p;
    cudaGetSymbolAddress((void**)&xhi_p,  g_xhi);
    cudaGetSymbolAddress((void**)&xlo_p,  g_xlo);
    cudaGetSymbolAddress((void**)&hhi_p,  g_hhi);
    cudaGetSymbolAddress((void**)&hlo_p,  g_hlo);
    cudaGetSymbolAddress((void**)&h2hi_p, g_h2hi);
    cudaGetSymbolAddress((void**)&h2lo_p, g_h2lo);
    cudaGetSymbolAddress((void**)&h32_p,  g_h32);
    cudaGetSymbolAddress((void**)&h232_p, g_h232);
    cudaGetSymbolAddress((void**)&wihh_p, g_wih_hi);
    cudaGetSymbolAddress((void**)&wihl_p, g_wih_lo);
    cudaGetSymbolAddress((void**)&whhh_p, g_whh_hi);
    cudaGetSymbolAddress((void**)&whhl_p, g_whh_lo);

    dim3 grid(MTOT / (64 * NTILES), 4);    // (32, 4)
    // pass 1: x = a, h = ev  -> h1 (fp32 + bf16 splits into fresh buffers)
    gru_pass_kernel<<<grid, 256, SMEM_TOT>>>(
        xhi_p, xlo_p, hhi_p, hlo_p, h32_p,
        wihh_p, wihl_p, whhh_p, whhl_p, b_ih, b_hh,
        h232_p, h2hi_p, h2lo_p);
    // pass 2: x = h = h1 -> d_out
    gru_pass_kernel<<<grid, 256, SMEM_TOT>>>(
        h2hi_p, h2lo_p, h2hi_p, h2lo_p, h232_p,
        wihh_p, wihl_p, whhh_p, whhl_p, b_ih, b_hh,
        out, nullptr, nullptr);
}

// round 10
// speedup vs baseline: 2.0751x; 1.2949x over previous
#include <cuda_runtime.h>
#include <cuda_fp16.h>
#include <cstdint>

#define B_    256
#define NI    64
#define L_    128
#define H_    128
#define K_    40
#define MTOT  (B_ * K_)          /* 10240 rows */
#define GATES 384

typedef unsigned long long ull;

// ---------------------------------------------------------------------------
// Device scratch (fp16 activations/weights; fp32 hold state)
// ---------------------------------------------------------------------------
__device__ __align__(256) __half g_x16[MTOT * H_];
__device__ __align__(256) __half g_h16[MTOT * H_];
__device__ __align__(256) float  g_h32[MTOT * H_];
__device__ __align__(256) __half g_h216[MTOT * H_];
__device__ __align__(256) float  g_h232[MTOT * H_];
__device__ __align__(256) __half g_wih_hi[GATES * H_];
__device__ __align__(256) __half g_wih_lo[GATES * H_];
__device__ __align__(256) __half g_whh_hi[GATES * H_];
__device__ __align__(256) __half g_whh_lo[GATES * H_];

// ---------------------------------------------------------------------------
// Helpers
// ---------------------------------------------------------------------------
__device__ __forceinline__ uint32_t smem_u32(const void* p) {
    uint32_t a;
    asm("{ .reg .u64 t; cvta.to.shared.u64 t, %1; cvt.u32.u64 %0, t; }"
        : "=r"(a) : "l"(p));
    return a;
}
__device__ __forceinline__ void cp16(uint32_t dst, const void* src) {
    asm volatile("cp.async.cg.shared.global [%0], [%1], 16;"
                 :: "r"(dst), "l"(src) : "memory");
}
#define CP_COMMIT() asm volatile("cp.async.commit_group;" ::: "memory")
#define CP_WAIT0()  asm volatile("cp.async.wait_group 0;" ::: "memory")
#define NB(id)      asm volatile("bar.sync %0, 128;" :: "r"((id) + 1) : "memory")

__device__ __forceinline__ void ldm4(uint32_t* a, uint32_t addr) {
    asm volatile("ldmatrix.sync.aligned.m8n8.x4.shared.b16 {%0,%1,%2,%3}, [%4];"
                 : "=r"(a[0]), "=r"(a[1]), "=r"(a[2]), "=r"(a[3]) : "r"(addr));
}
__device__ __forceinline__ void ldm2(uint32_t* a, uint32_t addr) {
    asm volatile("ldmatrix.sync.aligned.m8n8.x2.shared.b16 {%0,%1}, [%2];"
                 : "=r"(a[0]), "=r"(a[1]) : "r"(addr));
}
__device__ __forceinline__ float2 lds2f(uint32_t addr) {
    float2 v;
    asm volatile("ld.shared.v2.f32 {%0,%1}, [%2];"
                 : "=f"(v.x), "=f"(v.y) : "r"(addr));
    return v;
}
__device__ __forceinline__ void hmma(float* c, const uint32_t* a,
                                     uint32_t b0, uint32_t b1) {
    asm volatile("mma.sync.aligned.m16n8k16.row.col.f32.f16.f16.f32 "
                 "{%0,%1,%2,%3}, {%4,%5,%6,%7}, {%8,%9}, {%0,%1,%2,%3};"
                 : "+f"(c[0]), "+f"(c[1]), "+f"(c[2]), "+f"(c[3])
                 : "r"(a[0]), "r"(a[1]), "r"(a[2]), "r"(a[3]),
                   "r"(b0), "r"(b1));
}

__device__ __forceinline__ ull pk2(float v) {
    ull r; asm("mov.b64 %0, {%1, %1};" : "=l"(r) : "f"(v)); return r;
}
__device__ __forceinline__ float2 upk(ull v) {
    float2 f; asm("mov.b64 {%0, %1}, %2;" : "=f"(f.x), "=f"(f.y) : "l"(v)); return f;
}
__device__ __forceinline__ void fma2(ull& d, ull a, ull b) {
    asm("fma.rn.f32x2 %0, %1, %2, %0;" : "+l"(d) : "l"(a), "l"(b));
}
__device__ __forceinline__ ull ld2(const float* p) { return *(const ull*)p; }

__device__ __forceinline__ float sigm(float x) {
    return __fdividef(1.0f, 1.0f + __expf(-x));
}
__device__ __forceinline__ float tanh_(float x) {
    return __fdividef(2.0f, 1.0f + __expf(-2.0f * x)) - 1.0f;
}
// pack two floats into f16x2 (lo = a, hi = b)
__device__ __forceinline__ uint32_t f16x2_of(float a, float b) {
    uint32_t r;
    asm("cvt.rn.f16x2.f32 %0, %1, %2;" : "=r"(r) : "f"(b), "f"(a));
    return r;
}

// ---------------------------------------------------------------------------
// K1: split weights into fp16 hi/lo
// ---------------------------------------------------------------------------
__global__ void prep_kernel(const float* __restrict__ w_ih,
                            const float* __restrict__ w_hh) {
    int idx = blockIdx.x * blockDim.x + threadIdx.x;
    if (idx < GATES * H_) {
        float wi = w_ih[idx];
        __half hi = __float2half(wi);
        g_wih_hi[idx] = hi;
        g_wih_lo[idx] = __float2half(wi - __half2float(hi));
        float wh = w_hh[idx];
        __half hh = __float2half(wh);
        g_whh_hi[idx] = hh;
        g_whh_lo[idx] = __float2half(wh - __half2float(hh));
    }
}

// ---------------------------------------------------------------------------
// K2: gather + adj GEMM -> x (a) fp16, h (ev) fp16 + fp32 hold.
// ---------------------------------------------------------------------------
__global__ __launch_bounds__(256, 1)
void gather_adj_kernel(const float* __restrict__ seq_out,
                       const int*   __restrict__ target_idxs,
                       const int*   __restrict__ nid2rows,
                       const int*   __restrict__ ev_nids,
                       const float* __restrict__ adj,
                       const float* __restrict__ adj_bias) {
    __shared__ float s_h[K_ * H_];
    __shared__ float s_adj[K_ * K_];

    const int b    = blockIdx.x;
    const int tid  = threadIdx.x;
    const int warp = tid >> 5;
    const int lane = tid & 31;
    const int r0   = warp * 5;
    const int c0   = lane * 2;
    const int c1   = lane * 2 + 64;

    for (int i = tid; i < K_ * K_; i += 256)
        s_adj[i] = adj[b * K_ * K_ + i];

    #pragma unroll
    for (int rr = 0; rr < 5; rr++) {
        int k   = r0 + rr;
        int nid = ev_nids[b * K_ + k];
        int row = nid2rows[b * NI + nid];
        long long gi = (long long)b * NI + row;
        int t = target_idxs[gi];
        const float4* src = reinterpret_cast<const float4*>(
            seq_out + (gi * L_ + t) * (long long)H_);
        reinterpret_cast<float4*>(s_h + k * H_)[lane] = src[lane];
    }
    __syncthreads();

    ull bias0 = ld2(adj_bias + c0);
    ull bias1 = ld2(adj_bias + c1);
    ull acc[5][2];
    #pragma unroll
    for (int r = 0; r < 5; r++) { acc[r][0] = bias0; acc[r][1] = bias1; }

    for (int i = 0; i < K_; i++) {
        ull e0 = ld2(s_h + i * H_ + c0);
        ull e1 = ld2(s_h + i * H_ + c1);
        #pragma unroll
        for (int r = 0; r < 5; r++) {
            ull av = pk2(s_adj[i * K_ + r0 + r]);
            fma2(acc[r][0], av, e0);
            fma2(acc[r][1], av, e1);
        }
    }

    #pragma unroll
    for (int r = 0; r < 5; r++) {
        int gr = b * K_ + r0 + r;
        float2 a0 = upk(acc[r][0]);
        float2 a1 = upk(acc[r][1]);
        *(uint32_t*)(g_x16 + gr * H_ + c0) = f16x2_of(a0.x, a0.y);
        *(uint32_t*)(g_x16 + gr * H_ + c1) = f16x2_of(a1.x, a1.y);

        float2 e0 = upk(ld2(s_h + (r0 + r) * H_ + c0));
        float2 e1 = upk(ld2(s_h + (r0 + r) * H_ + c1));
        *(float2*)(g_h32 + gr * H_ + c0) = e0;
        *(float2*)(g_h32 + gr * H_ + c1) = e1;
        *(uint32_t*)(g_h16 + gr * H_ + c0) = f16x2_of(e0.x, e0.y);
        *(uint32_t*)(g_h16 + gr * H_ + c1) = f16x2_of(e1.x, e1.y);
    }
}

// ---------------------------------------------------------------------------
// K3: one GRU pass via fp16 HMMA, 2-term split (x16*whi + x16*wlo).
// Grid (32, 4), 256 threads = 8 warps = 4 col-groups (8 h-cols) x 2 row-groups
// (32 rows).  All 6 gate blocks per warp -> pure register GRU combine.
// whi/whh_hi fragments register-resident (96 regs); wlo streamed (ldmatrix.x2);
// hold prefetched to double-buffered smem with the A cp.async.
// ---------------------------------------------------------------------------
#define PITCH    272                      /* bytes per A/W smem row */
#define A_TSZ    (64 * PITCH)             /* 17408 */
#define SW_OFF   (2 * A_TSZ)              /* 34816 */
#define W_TSZ    (192 * PITCH)            /* 52224 */
#define HOLD_OFF (SW_OFF + 2 * W_TSZ)     /* 139264 */
#define HPITCHB  144                      /* 36 floats, 16B aligned rows */
#define HOLD_SZ  (64 * HPITCHB)           /* 9216 */
#define SMEM_TOT (HOLD_OFF + 2 * HOLD_SZ) /* 157696 */
#define NTILES   5

__global__ __launch_bounds__(256, 1)
void gru_pass_kernel(const __half* __restrict__ x16,
                     const __half* __restrict__ h16,
                     const float* __restrict__ hold,
                     const __half* __restrict__ wih_hi,
                     const __half* __restrict__ wih_lo,
                     const __half* __restrict__ whh_hi,
                     const __half* __restrict__ whh_lo,
                     const float* __restrict__ b_ih,
                     const float* __restrict__ b_hh,
                     float* __restrict__ out32,
                     __half* __restrict__ out16) {
    extern __shared__ __align__(16) char smem[];
    const uint32_t sb  = smem_u32(smem);
    const int tid   = threadIdx.x;
    const int wid   = tid >> 5;
    const int lane  = tid & 31;
    const int ycol0 = blockIdx.y * 32;
    const int m0    = blockIdx.x * NTILES;      // first M-tile

    const int cg    = wid >> 1;            // 0..3 col group (8 h-cols)
    const int rowg  = wid & 1;             // 0..1 row group (32 rows)
    const int mrows = rowg * 32;
    const int gt    = cg * 32 + lane;      // group-local tid 0..127

    // ---- per-group prefetch: A slices (x16, h16) + hold ---------------------
    const __half* asrc[2] = {x16, h16};
    auto loadA = [&](int m, int pb) {
        #pragma unroll
        for (int t2 = 0; t2 < 2; t2++) {
            const __half* src = asrc[t2] + ((size_t)m * 64 + mrows) * H_;
            uint32_t dst = sb + t2 * A_TSZ + mrows * PITCH;
            #pragma unroll
            for (int c = gt; c < 512; c += 128) {       // 32 rows x 16 chunks
                int row = c >> 4, cw = c & 15;
                cp16(dst + row * PITCH + cw * 16, src + row * H_ + cw * 8);
            }
        }
        // hold slice: 32 rows x 32 cols f32 (8 chunks/row)
        {
            const float* src = hold + ((size_t)m * 64 + mrows) * H_ + ycol0;
            uint32_t dst = sb + HOLD_OFF + pb * HOLD_SZ + mrows * HPITCHB;
            #pragma unroll
            for (int c = gt; c < 256; c += 128) {       // 32 rows x 8 chunks
                int row = c >> 3, cw = c & 7;
                cp16(dst + row * HPITCHB + cw * 16, src + row * H_ + cw * 4);
            }
        }
    };

    // ---- W load (once): 192 gate-rows x 128 k, hi then lo ------------------
    {
        const __half* wsrc[4] = {wih_hi, whh_hi, wih_lo, whh_lo};
        #pragma unroll
        for (int part = 0; part < 2; part++) {
            uint32_t dst = sb + SW_OFF + part * W_TSZ;
            #pragma unroll
            for (int c = tid; c < 3072; c += 256) {     // 192 rows x 16 chunks
                int gp = c >> 4, cw = c & 15;
                int sde = gp / 96, rem = gp % 96;
                int gate = rem >> 5, hc = rem & 31;
                const __half* src = wsrc[part * 2 + sde]
                    + (size_t)(gate * H_ + ycol0 + hc) * H_ + cw * 8;
                cp16(dst + gp * PITCH + cw * 16, src);
            }
        }
    }
    loadA(m0, 0);
    CP_COMMIT();
    CP_WAIT0();
    __syncthreads();                       // W + first A/hold visible

    // ---- fragment address constants -----------------------------------------
    const uint32_t a_lanoff = (uint32_t)(lane & 15) * PITCH
                            + ((lane >> 4) & 1) * 16;
    const int l15 = lane & 15;
    const uint32_t b_lanoff = (uint32_t)(l15 & 7) * PITCH + (l15 >> 3) * 16;

    // W row offset per gate block (0..2: ih r/z/n, 3..5: hh r/z/n)
    uint32_t wrow_off[6];
    #pragma unroll
    for (int blk = 0; blk < 6; blk++) {
        int sde = blk / 3, gate = blk % 3;
        wrow_off[blk] = (uint32_t)(sde * 96 + gate * 32 + cg * 8) * PITCH
                      + b_lanoff;
    }

    // ---- resident hi-weight fragments (96 regs) -----------------------------
    uint32_t bw[8][6][2];
    #pragma unroll
    for (int ks = 0; ks < 8; ks++)
        #pragma unroll
        for (int blk = 0; blk < 6; blk++)
            ldm2(bw[ks][blk], sb + SW_OFF + wrow_off[blk] + ks * 32);

    // ---- epilogue constants (biases hoisted) ---------------------------------
    const int e_colp = ycol0 + cg * 8 + (lane & 3) * 2;   // even col pair base
    const float2 BIr = *(const float2*)(b_ih + e_colp);
    const float2 BIz = *(const float2*)(b_ih + 128 + e_colp);
    const float2 BIn = *(const float2*)(b_ih + 256 + e_colp);
    const float2 BHr = *(const float2*)(b_hh + e_colp);
    const float2 BHz = *(const float2*)(b_hh + 128 + e_colp);
    const float2 BHn = *(const float2*)(b_hh + 256 + e_colp);
    const uint32_t h_lanoff = (uint32_t)(cg * 8 + (lane & 3) * 2) * 4;

    int pb = 0;
    #pragma unroll 1
    for (int it = 0; it < NTILES; it++) {
        const int m     = m0 + it;
        const int mrow0 = m * 64;

        // ---- MMA compute: all 6 gate blocks, 2-term fp16 split ----------------
        float acc[2][6][4];
        #pragma unroll
        for (int mt = 0; mt < 2; mt++)
            #pragma unroll
            for (int j = 0; j < 6; j++)
                #pragma unroll
                for (int q = 0; q < 4; q++) acc[mt][j][q] = 0.0f;

        const uint32_t Ax = sb + 0 * A_TSZ + mrows * PITCH + a_lanoff; // x16
        const uint32_t Ah = sb + 1 * A_TSZ + mrows * PITCH + a_lanoff; // h16
        const uint32_t Blo = sb + SW_OFF + W_TSZ;

        #pragma unroll
        for (int ks = 0; ks < 8; ks++) {
            uint32_t xf[2][4], hf[2][4];
            ldm4(xf[0], Ax + ks * 32);
            ldm4(xf[1], Ax + ks * 32 + 16 * PITCH);
            ldm4(hf[0], Ah + ks * 32);
            ldm4(hf[1], Ah + ks * 32 + 16 * PITCH);

            #pragma unroll
            for (int blk = 0; blk < 6; blk++) {
                const uint32_t* a0 = (blk < 3) ? xf[0] : hf[0];
                const uint32_t* a1 = (blk < 3) ? xf[1] : hf[1];
                uint32_t w0 = bw[ks][blk][0], w1 = bw[ks][blk][1];
                // term 1: a * w_hi (resident)
                hmma(acc[0][blk], a0, w0, w1);
                hmma(acc[1][blk], a1, w0, w1);
                // term 2: a * w_lo (streamed)
                uint32_t bl[2];
                ldm2(bl, Blo + wrow_off[blk] + ks * 32);
                hmma(acc[0][blk], a0, bl[0], bl[1]);
                hmma(acc[1][blk], a1, bl[0], bl[1]);
            }
        }
        NB(rowg);                          // group's A slice fully consumed

        // ---- prefetch next A + hold (overlaps epilogue) -----------------------
        if (it + 1 < NTILES) { loadA(m + 1, pb ^ 1); CP_COMMIT(); }

        // ---- register epilogue: combine gates -> h' ---------------------------
        const uint32_t hbase = sb + HOLD_OFF + pb * HOLD_SZ + h_lanoff;
        #pragma unroll
        for (int mt = 0; mt < 2; mt++) {
            #pragma unroll
            for (int half = 0; half < 2; half++) {
                int row  = mrows + mt * 16 + (lane >> 2) + half * 8;
                int q0   = half * 2;
                float2 ho = lds2f(hbase + row * HPITCHB);
                float r0 = sigm(acc[mt][0][q0]     + BIr.x + acc[mt][3][q0]     + BHr.x);
                float r1 = sigm(acc[mt][0][q0 + 1] + BIr.y + acc[mt][3][q0 + 1] + BHr.y);
                float z0 = sigm(acc[mt][1][q0]     + BIz.x + acc[mt][4][q0]     + BHz.x);
                float z1 = sigm(acc[mt][1][q0 + 1] + BIz.y + acc[mt][4][q0 + 1] + BHz.y);
                float n0 = tanh_(acc[mt][2][q0]     + BIn.x + r0 * (acc[mt][5][q0]     + BHn.x));
                float n1 = tanh_(acc[mt][2][q0 + 1] + BIn.y + r1 * (acc[mt][5][q0 + 1] + BHn.y));
                float hn0 = (1.0f - z0) * n0 + z0 * ho.x;
                float hn1 = (1.0f - z1) * n1 + z1 * ho.y;
                long long idx = (long long)(mrow0 + row) * H_ + e_colp;
                *(float2*)(out32 + idx) = make_float2(hn0, hn1);
                if (out16)
                    *(uint32_t*)(out16 + idx) = f16x2_of(hn0, hn1);
            }
        }

        if (it + 1 < NTILES) { CP_WAIT0(); }
        NB(rowg);                          // next A/hold ready for whole group
        pb ^= 1;
    }
}

// ---------------------------------------------------------------------------
extern "C" void kernel_launch(void* const* d_in, const int* in_sizes, int n_in,
                              void* d_out, int out_size) {
    const float* seq_out     = (const float*)d_in[0];
    const int*   target_idxs = (const int*)  d_in[1];
    const int*   nid2rows    = (const int*)  d_in[2];
    const int*   ev_nids     = (const int*)  d_in[3];
    const float* adj         = (const float*)d_in[4];
    const float* adj_bias    = (const float*)d_in[5];
    const float* w_ih        = (const float*)d_in[6];
    const float* w_hh        = (const float*)d_in[7];
    const float* b_ih        = (const float*)d_in[8];
    const float* b_hh        = (const float*)d_in[9];
    float* out = (float*)d_out;

    static bool attr_set = false;
    if (!attr_set) {
        cudaFuncSetAttribute(gru_pass_kernel,
                             cudaFuncAttributeMaxDynamicSharedMemorySize,
                             SMEM_TOT);
        attr_set = true;
    }

    prep_kernel<<<(GATES * H_ + 255) / 256, 256>>>(w_ih, w_hh);
    gather_adj_kernel<<<B_, 256>>>(seq_out, target_idxs, nid2rows, ev_nids,
                                   adj, adj_bias);

    __half *x16_p, *h16_p, *h216_p;
    __half *wihh_p, *wihl_p, *whhh_p, *whhl_p;
    float *h32_p, *h232_p;
    cudaGetSymbolAddress((void**)&x16_p,  g_x16);
    cudaGetSymbolAddress((void**)&h16_p,  g_h16);
    cudaGetSymbolAddress((void**)&h216_p, g_h216);
    cudaGetSymbolAddress((void**)&h32_p,  g_h32);
    cudaGetSymbolAddress((void**)&h232_p, g_h232);
    cudaGetSymbolAddress((void**)&wihh_p, g_wih_hi);
    cudaGetSymbolAddress((void**)&wihl_p, g_wih_lo);
    cudaGetSymbolAddress((void**)&whhh_p, g_whh_hi);
    cudaGetSymbolAddress((void**)&whhl_p, g_whh_lo);

    dim3 grid(MTOT / (64 * NTILES), 4);    // (32, 4)
    // pass 1: x = a, h = ev  -> h1 (fp32 + fp16 into fresh buffers)
    gru_pass_kernel<<<grid, 256, SMEM_TOT>>>(
        x16_p, h16_p, h32_p,
        wihh_p, wihl_p, whhh_p, whhl_p, b_ih, b_hh,
        h232_p, h216_p);
    // pass 2: x = h = h1 -> d_out
    gru_pass_kernel<<<grid, 256, SMEM_TOT>>>(
        h216_p, h216_p, h232_p,
        wihh_p, wihl_p, whhh_p, whhl_p, b_ih, b_hh,
        out, nullptr);
}